// round 1
// baseline (speedup 1.0000x reference)
#include <cuda_runtime.h>
#include <math.h>

// ---------------------------------------------------------------------------
// Problem constants: B=8, L=1024, D=1024, H=16, d=64
//   M = B*L = 8192 token rows, all GEMMs are [8192,1024] x [1024,1024]^T
//   Attention: 128 independent units of Q,K,V [1024,64] (raw-view head split)
// ---------------------------------------------------------------------------

#define M_ROWS  8192
#define DIM     1024
#define NCHUNK  128        // B*H
#define CHUNK_ELEMS 65536  // 1024*64

// Scratch (device globals: allocation-free)
__device__ float g_q[M_ROWS * DIM];
__device__ float g_k[M_ROWS * DIM];
__device__ float g_v[M_ROWS * DIM];
__device__ float g_ctx[M_ROWS * DIM];
__device__ float g_proj[M_ROWS * DIM];

// ---------------------------------------------------------------------------
// GEMM (NT):  C[M,N] = A[M,K] @ W[N,K]^T + bias[N]
// M=8192, N=K=1024.  128x128 tile, BK=8, 256 threads, 8x8 microtile.
// ---------------------------------------------------------------------------
__global__ void __launch_bounds__(256) gemm_nt_bias(
    const float* __restrict__ A, const float* __restrict__ W,
    const float* __restrict__ bias, float* __restrict__ C)
{
    const int K = DIM, N = DIM;
    __shared__ float As[8][128];
    __shared__ float Bs[8][128];

    const int tid  = threadIdx.x;
    const int tx   = tid & 15;       // 0..15 -> C cols
    const int ty   = tid >> 4;       // 0..15 -> C rows
    const int row0 = blockIdx.y * 128;
    const int col0 = blockIdx.x * 128;

    const int lrow = tid >> 1;          // 0..127
    const int lc   = (tid & 1) * 4;     // 0 or 4

    const float* Ap = A + (size_t)(row0 + lrow) * K + lc;
    const float* Wp = W + (size_t)(col0 + lrow) * K + lc;

    float acc[8][8] = {};

    for (int k0 = 0; k0 < K; k0 += 8) {
        float4 av = *(const float4*)(Ap + k0);
        float4 wv = *(const float4*)(Wp + k0);
        As[lc + 0][lrow] = av.x; As[lc + 1][lrow] = av.y;
        As[lc + 2][lrow] = av.z; As[lc + 3][lrow] = av.w;
        Bs[lc + 0][lrow] = wv.x; Bs[lc + 1][lrow] = wv.y;
        Bs[lc + 2][lrow] = wv.z; Bs[lc + 3][lrow] = wv.w;
        __syncthreads();

        #pragma unroll
        for (int k = 0; k < 8; k++) {
            float a[8], b[8];
            *(float4*)&a[0] = *(const float4*)&As[k][ty * 8];
            *(float4*)&a[4] = *(const float4*)&As[k][ty * 8 + 4];
            *(float4*)&b[0] = *(const float4*)&Bs[k][tx * 8];
            *(float4*)&b[4] = *(const float4*)&Bs[k][tx * 8 + 4];
            #pragma unroll
            for (int i = 0; i < 8; i++)
                #pragma unroll
                for (int j = 0; j < 8; j++)
                    acc[i][j] = fmaf(a[i], b[j], acc[i][j]);
        }
        __syncthreads();
    }

    #pragma unroll
    for (int i = 0; i < 8; i++) {
        float* Cp = C + (size_t)(row0 + ty * 8 + i) * N + col0 + tx * 8;
        #pragma unroll
        for (int jq = 0; jq < 8; jq += 4) {
            float4 o;
            o.x = acc[i][jq + 0] + bias[col0 + tx * 8 + jq + 0];
            o.y = acc[i][jq + 1] + bias[col0 + tx * 8 + jq + 1];
            o.z = acc[i][jq + 2] + bias[col0 + tx * 8 + jq + 2];
            o.w = acc[i][jq + 3] + bias[col0 + tx * 8 + jq + 3];
            *(float4*)(Cp + jq) = o;
        }
    }
}

// ---------------------------------------------------------------------------
// Attention: per CTA -> one chunk r (0..127) and one 128-row q-tile (0..7).
// Streaming over 8 k-tiles of 128:
//   S = Q Kt^T / 8 ; P = mask==0 ? 0 : exp(S) ; O += P V ; rowsum += P.
// Final: O /= max(rowsum, 2e-15).  Matches the unstable-exp reference exactly.
// smem: Qst[64][132] (Q^T), Kst[64][132] (K^T), Vs[128][64], Ps[128][128]
// ---------------------------------------------------------------------------
#define PADT 132
#define ATTN_SMEM_FLOATS (64*PADT + 64*PADT + 128*64 + 128*128 + 256)
#define ATTN_SMEM_BYTES  (ATTN_SMEM_FLOATS * 4)

__global__ void __launch_bounds__(256) attn_kernel(
    const float* __restrict__ qmask, const float* __restrict__ kmask)
{
    extern __shared__ float sm[];
    float* Qst = sm;                  // [64][132]
    float* Kst = Qst + 64 * PADT;     // [64][132]
    float* Vs  = Kst + 64 * PADT;     // [128][64]
    float* Ps  = Vs + 128 * 64;       // [128][128]
    float* qmr = Ps + 128 * 128;      // [128]
    float* kmr = qmr + 128;           // [128]

    const int tid = threadIdx.x;
    const int tx  = tid & 15;   // 0..15
    const int ty  = tid >> 4;   // 0..15
    const int r   = blockIdx.x; // chunk
    const int qt  = blockIdx.y; // q tile

    const float* Qc = g_q + (size_t)r * CHUNK_ELEMS + qt * 8192;
    const float* Kc = g_k + (size_t)r * CHUNK_ELEMS;
    const float* Vc = g_v + (size_t)r * CHUNK_ELEMS;

    // Load Q tile transposed: Qst[c][row] = Qc[row][c]
    for (int idx = tid; idx < 8192; idx += 256)
        Qst[(idx & 63) * PADT + (idx >> 6)] = Qc[idx];
    if (tid < 128)
        qmr[tid] = qmask[(r & 7) * 1024 + qt * 128 + tid];

    float oacc[8][4] = {};
    float rs[8] = {};

    for (int kt = 0; kt < 8; kt++) {
        __syncthreads();   // prev P@V done (Vs/Ps free), Qst ready on iter 0
        for (int idx = tid; idx < 8192; idx += 256)
            Kst[(idx & 63) * PADT + (idx >> 6)] = Kc[kt * 8192 + idx];
        for (int idx = tid; idx < 2048; idx += 256)
            ((float4*)Vs)[idx] = ((const float4*)(Vc + kt * 8192))[idx];
        if (tid < 128)
            kmr[tid] = kmask[(r & 7) * 1024 + kt * 128 + tid];
        __syncthreads();

        // S = Q @ K^T  (8x8 fragment per thread)
        float s[8][8] = {};
        #pragma unroll 8
        for (int kk = 0; kk < 64; kk++) {
            float a[8], b[8];
            *(float4*)&a[0] = *(const float4*)&Qst[kk * PADT + ty * 8];
            *(float4*)&a[4] = *(const float4*)&Qst[kk * PADT + ty * 8 + 4];
            *(float4*)&b[0] = *(const float4*)&Kst[kk * PADT + tx * 8];
            *(float4*)&b[4] = *(const float4*)&Kst[kk * PADT + tx * 8 + 4];
            #pragma unroll
            for (int i = 0; i < 8; i++)
                #pragma unroll
                for (int j = 0; j < 8; j++)
                    s[i][j] = fmaf(a[i], b[j], s[i][j]);
        }

        // P = exp(S/8) with mask; accumulate row sums; spill P to smem
        #pragma unroll
        for (int i = 0; i < 8; i++) {
            float qm = qmr[ty * 8 + i];
            #pragma unroll
            for (int j = 0; j < 8; j++) {
                float p = (qm * kmr[tx * 8 + j] == 0.0f)
                              ? 0.0f : __expf(s[i][j] * 0.125f);
                rs[i] += p;
                s[i][j] = p;
            }
            *(float4*)&Ps[(ty * 8 + i) * 128 + tx * 8]     = *(float4*)&s[i][0];
            *(float4*)&Ps[(ty * 8 + i) * 128 + tx * 8 + 4] = *(float4*)&s[i][4];
        }
        __syncthreads();

        // O += P @ V  (8 rows x 4 cols per thread, a-loads are warp broadcasts)
        #pragma unroll 4
        for (int j = 0; j < 128; j++) {
            float4 bv = *(const float4*)&Vs[j * 64 + tx * 4];
            #pragma unroll
            for (int i = 0; i < 8; i++) {
                float a = Ps[(ty * 8 + i) * 128 + j];
                oacc[i][0] = fmaf(a, bv.x, oacc[i][0]);
                oacc[i][1] = fmaf(a, bv.y, oacc[i][1]);
                oacc[i][2] = fmaf(a, bv.z, oacc[i][2]);
                oacc[i][3] = fmaf(a, bv.w, oacc[i][3]);
            }
        }
    }

    // Row-sum reduction across the 16 threads sharing a row (16-lane groups)
    float* Oc = g_ctx + (size_t)r * CHUNK_ELEMS + qt * 8192;
    #pragma unroll
    for (int i = 0; i < 8; i++) {
        float v = rs[i];
        v += __shfl_xor_sync(0xffffffffu, v, 1);
        v += __shfl_xor_sync(0xffffffffu, v, 2);
        v += __shfl_xor_sync(0xffffffffu, v, 4);
        v += __shfl_xor_sync(0xffffffffu, v, 8);
        float inv = 1.0f / fmaxf(v, 2e-15f);
        float4 o = make_float4(oacc[i][0] * inv, oacc[i][1] * inv,
                               oacc[i][2] * inv, oacc[i][3] * inv);
        *(float4*)&Oc[(ty * 8 + i) * 64 + tx * 4] = o;
    }
}

// ---------------------------------------------------------------------------
// Residual add + LayerNorm (two-pass mean/var exactly like reference)
// One CTA per row; 256 threads x 4 elems.
// ---------------------------------------------------------------------------
__global__ void __launch_bounds__(256) resid_ln_kernel(
    const float* __restrict__ resid, const float* __restrict__ gamma,
    const float* __restrict__ beta, float* __restrict__ out)
{
    __shared__ float red[8];
    __shared__ float bc;

    const int row = blockIdx.x;
    const int tid = threadIdx.x;
    const float* pr = g_proj + (size_t)row * 1024;
    const float* rr = resid + (size_t)row * 1024;

    float x[4];
    float sum = 0.0f;
    #pragma unroll
    for (int c = 0; c < 4; c++) {
        x[c] = rr[tid + 256 * c] + pr[tid + 256 * c];
        sum += x[c];
    }
    #pragma unroll
    for (int m = 16; m; m >>= 1) sum += __shfl_xor_sync(0xffffffffu, sum, m);
    if ((tid & 31) == 0) red[tid >> 5] = sum;
    __syncthreads();
    if (tid == 0) {
        float t = 0.0f;
        #pragma unroll
        for (int i = 0; i < 8; i++) t += red[i];
        bc = t;
    }
    __syncthreads();
    const float mean = bc * (1.0f / 1024.0f);

    float vs = 0.0f;
    #pragma unroll
    for (int c = 0; c < 4; c++) { float d = x[c] - mean; vs += d * d; }
    #pragma unroll
    for (int m = 16; m; m >>= 1) vs += __shfl_xor_sync(0xffffffffu, vs, m);
    __syncthreads();   // red reuse: ensure everyone is past the mean phase
    if ((tid & 31) == 0) red[tid >> 5] = vs;
    __syncthreads();
    if (tid == 0) {
        float t = 0.0f;
        #pragma unroll
        for (int i = 0; i < 8; i++) t += red[i];
        bc = t;
    }
    __syncthreads();
    const float var = bc * (1.0f / 1024.0f);
    const float inv = rsqrtf(var + 1e-5f);

    #pragma unroll
    for (int c = 0; c < 4; c++) {
        int idx = tid + 256 * c;
        out[(size_t)row * 1024 + idx] =
            (x[c] - mean) * inv * gamma[idx] + beta[idx];
    }
}

// ---------------------------------------------------------------------------
// Host launcher
// ---------------------------------------------------------------------------
extern "C" void kernel_launch(void* const* d_in, const int* in_sizes, int n_in,
                              void* d_out, int out_size)
{
    const float* query  = (const float*)d_in[0];
    const float* key    = (const float*)d_in[1];
    const float* value  = (const float*)d_in[2];
    const float* q_mask = (const float*)d_in[3];
    const float* k_mask = (const float*)d_in[4];
    const float* Wq     = (const float*)d_in[5];
    const float* bq     = (const float*)d_in[6];
    const float* Wk     = (const float*)d_in[7];
    const float* bk     = (const float*)d_in[8];
    const float* Wv     = (const float*)d_in[9];
    const float* bv     = (const float*)d_in[10];
    const float* Wo     = (const float*)d_in[11];
    const float* bo     = (const float*)d_in[12];
    const float* gamma  = (const float*)d_in[13];
    const float* beta   = (const float*)d_in[14];
    float* out = (float*)d_out;

    (void)in_sizes; (void)n_in; (void)out_size;

    cudaFuncSetAttribute(attn_kernel,
                         cudaFuncAttributeMaxDynamicSharedMemorySize,
                         ATTN_SMEM_BYTES);

    float *gq, *gk, *gv, *gctx, *gproj;
    cudaGetSymbolAddress((void**)&gq,    g_q);
    cudaGetSymbolAddress((void**)&gk,    g_k);
    cudaGetSymbolAddress((void**)&gv,    g_v);
    cudaGetSymbolAddress((void**)&gctx,  g_ctx);
    cudaGetSymbolAddress((void**)&gproj, g_proj);

    dim3 ggrid(DIM / 128, M_ROWS / 128);   // (8, 64)

    gemm_nt_bias<<<ggrid, 256>>>(query, Wq, bq, gq);
    gemm_nt_bias<<<ggrid, 256>>>(key,   Wk, bk, gk);
    gemm_nt_bias<<<ggrid, 256>>>(value, Wv, bv, gv);

    attn_kernel<<<dim3(NCHUNK, 8), 256, ATTN_SMEM_BYTES>>>(q_mask, k_mask);

    gemm_nt_bias<<<ggrid, 256>>>(gctx, Wo, bo, gproj);

    resid_ln_kernel<<<M_ROWS, 256>>>(query, gamma, beta, out);
}

// round 4
// speedup vs baseline: 1.4232x; 1.4232x over previous
#include <cuda_runtime.h>
#include <cstdint>
#include <math.h>

// ---------------------------------------------------------------------------
// B=8, L=1024, D=1024, H=16, d=64.  M = 8192 token rows.
// GEMMs via warp-level mma.sync tf32 (base sm_103 PTX); attention fp32 SIMT.
// ---------------------------------------------------------------------------

#define M_ROWS  8192
#define DIM     1024
#define NCHUNK  128
#define CHUNK_ELEMS 65536

__device__ float g_q[M_ROWS * DIM];
__device__ float g_k[M_ROWS * DIM];
__device__ float g_v[M_ROWS * DIM];
__device__ float g_ctx[M_ROWS * DIM];
__device__ float g_proj[M_ROWS * DIM];

__device__ __forceinline__ uint32_t f2tf32(float x) {
    uint32_t u; asm("cvt.rna.tf32.f32 %0, %1;" : "=r"(u) : "f"(x)); return u;
}

__device__ __forceinline__ void mma_tf32(float* c, const uint32_t* a,
                                         const uint32_t* b) {
    asm volatile(
        "mma.sync.aligned.m16n8k8.row.col.f32.tf32.tf32.f32 "
        "{%0,%1,%2,%3}, {%4,%5,%6,%7}, {%8,%9}, {%0,%1,%2,%3};"
        : "+f"(c[0]), "+f"(c[1]), "+f"(c[2]), "+f"(c[3])
        : "r"(a[0]), "r"(a[1]), "r"(a[2]), "r"(a[3]), "r"(b[0]), "r"(b[1]));
}

// ---------------------------------------------------------------------------
// tf32 mma.sync GEMM: C[8192,1024] = A[8192,1024] @ W[1024,1024]^T + bias.
// CTA 128x128, 256 thr, warps 2(m)x4(n), warp tile 64x32. K chunks of 32.
//
// Fragment-major smem (PTX m16n8k8 tf32 layout):
//  A element (m,k) in 16x8 block: lane=(m%8)*4+(k%4), frag=2*(k>=4)+(m>=8)
//    off = (MT*4+ks)*160 + frag*40 + lane
//  B element (n,k) in  8x8 block: lane=(n%8)*4+(k%4), frag=(k>=4)
//    off = (NT*4+ks)*96 + frag*48 + lane
// ---------------------------------------------------------------------------
#define ABLK_STRIDE 160
#define AFRAG_STRIDE 40
#define BBLK_STRIDE 96
#define BFRAG_STRIDE 48
#define ABUF_FLOATS (32 * ABLK_STRIDE)          // 5120
#define BBUF_FLOATS (64 * BBLK_STRIDE)          // 6144
#define GBUF_FLOATS (ABUF_FLOATS + BBUF_FLOATS) // 11264
#define GT_SMEM_BYTES (2 * GBUF_FLOATS * 4)     // 90112

__global__ void __launch_bounds__(256, 1) gemm_mma_tf32(
    const float* __restrict__ A, const float* __restrict__ W,
    const float* __restrict__ bias, float* __restrict__ C)
{
    extern __shared__ float sm[];
    float* Abuf[2] = { sm, sm + GBUF_FLOATS };
    float* Bbuf[2] = { sm + ABUF_FLOATS, sm + GBUF_FLOATS + ABUF_FLOATS };

    const int tid  = threadIdx.x;
    const int lane = tid & 31;
    const int wid  = tid >> 5;
    const int wm   = wid & 1;     // 0..1  (64-row group)
    const int wn   = wid >> 1;    // 0..3  (32-col group)
    const int row0 = blockIdx.y * 128;
    const int col0 = blockIdx.x * 128;

    // loader mapping: row = tid>>1 (0..127), h = tid&1 -> k in [h*4, h*4+4)
    const int lrow = tid >> 1;
    const int h    = tid & 1;
    const float* Ap = A + (size_t)(row0 + lrow) * DIM + h * 4;
    const float* Wp = W + (size_t)(col0 + lrow) * DIM + h * 4;

    // A: frag = (m>=8) + 2*(k>=4) = a_f0 + 2h ; lane = (m%8)*4 + i
    const int a_f0 = (lrow >> 3) & 1;
    const int a_rp = lrow & 7;
    const int a_MT = lrow >> 4;
    const int a_base = a_MT * 4 * ABLK_STRIDE + (a_f0 + 2 * h) * AFRAG_STRIDE + a_rp * 4;
    // B: frag = (k>=4) = h ; lane = (n%8)*4 + i
    const int b_n  = lrow & 7;
    const int b_NT = lrow >> 3;
    const int b_base = b_NT * 4 * BBLK_STRIDE + h * BFRAG_STRIDE + b_n * 4;

    float4 ra[4], rb[4];
    #pragma unroll
    for (int j = 0; j < 4; j++) {
        ra[j] = *(const float4*)(Ap + j * 8);
        rb[j] = *(const float4*)(Wp + j * 8);
    }

    float acc[4][4][4];
    #pragma unroll
    for (int mt = 0; mt < 4; mt++)
        #pragma unroll
        for (int nt = 0; nt < 4; nt++)
            #pragma unroll
            for (int f = 0; f < 4; f++) acc[mt][nt][f] = 0.0f;

    // store chunk 0
    #pragma unroll
    for (int j = 0; j < 4; j++) {
        float4 ua, ub;
        ua.x = __uint_as_float(f2tf32(ra[j].x));
        ua.y = __uint_as_float(f2tf32(ra[j].y));
        ua.z = __uint_as_float(f2tf32(ra[j].z));
        ua.w = __uint_as_float(f2tf32(ra[j].w));
        ub.x = __uint_as_float(f2tf32(rb[j].x));
        ub.y = __uint_as_float(f2tf32(rb[j].y));
        ub.z = __uint_as_float(f2tf32(rb[j].z));
        ub.w = __uint_as_float(f2tf32(rb[j].w));
        *(float4*)(Abuf[0] + a_base + j * ABLK_STRIDE) = ua;
        *(float4*)(Bbuf[0] + b_base + j * BBLK_STRIDE) = ub;
    }
    __syncthreads();

    for (int c = 0; c < 32; ++c) {
        const int cur = c & 1, nxt = cur ^ 1;
        if (c < 31) {
            const float* Ap2 = Ap + (c + 1) * 32;
            const float* Wp2 = Wp + (c + 1) * 32;
            #pragma unroll
            for (int j = 0; j < 4; j++) {
                ra[j] = *(const float4*)(Ap2 + j * 8);
                rb[j] = *(const float4*)(Wp2 + j * 8);
            }
        }

        const float* ab = Abuf[cur];
        const float* bb = Bbuf[cur];
        #pragma unroll
        for (int ks = 0; ks < 4; ks++) {
            uint32_t afr[4][4], bfr[4][2];
            #pragma unroll
            for (int mt = 0; mt < 4; mt++) {
                const float* p = ab + ((wm * 4 + mt) * 4 + ks) * ABLK_STRIDE + lane;
                #pragma unroll
                for (int f = 0; f < 4; f++)
                    afr[mt][f] = __float_as_uint(p[f * AFRAG_STRIDE]);
            }
            #pragma unroll
            for (int nt = 0; nt < 4; nt++) {
                const float* p = bb + ((wn * 4 + nt) * 4 + ks) * BBLK_STRIDE + lane;
                #pragma unroll
                for (int f = 0; f < 2; f++)
                    bfr[nt][f] = __float_as_uint(p[f * BFRAG_STRIDE]);
            }
            #pragma unroll
            for (int mt = 0; mt < 4; mt++)
                #pragma unroll
                for (int nt = 0; nt < 4; nt++)
                    mma_tf32(acc[mt][nt], afr[mt], bfr[nt]);
        }

        if (c < 31) {
            #pragma unroll
            for (int j = 0; j < 4; j++) {
                float4 ua, ub;
                ua.x = __uint_as_float(f2tf32(ra[j].x));
                ua.y = __uint_as_float(f2tf32(ra[j].y));
                ua.z = __uint_as_float(f2tf32(ra[j].z));
                ua.w = __uint_as_float(f2tf32(ra[j].w));
                ub.x = __uint_as_float(f2tf32(rb[j].x));
                ub.y = __uint_as_float(f2tf32(rb[j].y));
                ub.z = __uint_as_float(f2tf32(rb[j].z));
                ub.w = __uint_as_float(f2tf32(rb[j].w));
                *(float4*)(Abuf[nxt] + a_base + j * ABLK_STRIDE) = ua;
                *(float4*)(Bbuf[nxt] + b_base + j * BBLK_STRIDE) = ub;
            }
        }
        __syncthreads();
    }

    // epilogue: c0,c1 -> (r, 2q),(r, 2q+1); c2,c3 -> (r+8, ...)
    const int qr = lane >> 2;        // 0..7
    const int qc = (lane & 3) * 2;   // 0,2,4,6
    #pragma unroll
    for (int nt = 0; nt < 4; nt++) {
        const int cc = col0 + wn * 32 + nt * 8 + qc;
        const float b0 = bias[cc], b1 = bias[cc + 1];
        #pragma unroll
        for (int mt = 0; mt < 4; mt++) {
            const int rr = row0 + wm * 64 + mt * 16 + qr;
            float2 o0 = make_float2(acc[mt][nt][0] + b0, acc[mt][nt][1] + b1);
            float2 o1 = make_float2(acc[mt][nt][2] + b0, acc[mt][nt][3] + b1);
            *(float2*)(C + (size_t)rr * DIM + cc)       = o0;
            *(float2*)(C + (size_t)(rr + 8) * DIM + cc) = o1;
        }
    }
}

// ---------------------------------------------------------------------------
// Attention (unchanged, passing @R1): per CTA one chunk r, one 128-row q tile.
// ---------------------------------------------------------------------------
#define PADT 132
#define ATTN_SMEM_FLOATS (64*PADT + 64*PADT + 128*64 + 128*128 + 256)
#define ATTN_SMEM_BYTES  (ATTN_SMEM_FLOATS * 4)

__global__ void __launch_bounds__(256) attn_kernel(
    const float* __restrict__ qmask, const float* __restrict__ kmask)
{
    extern __shared__ float sm[];
    float* Qst = sm;
    float* Kst = Qst + 64 * PADT;
    float* Vs  = Kst + 64 * PADT;
    float* Ps  = Vs + 128 * 64;
    float* qmr = Ps + 128 * 128;
    float* kmr = qmr + 128;

    const int tid = threadIdx.x;
    const int tx  = tid & 15;
    const int ty  = tid >> 4;
    const int r   = blockIdx.x;
    const int qt  = blockIdx.y;

    const float* Qc = g_q + (size_t)r * CHUNK_ELEMS + qt * 8192;
    const float* Kc = g_k + (size_t)r * CHUNK_ELEMS;
    const float* Vc = g_v + (size_t)r * CHUNK_ELEMS;

    for (int idx = tid; idx < 8192; idx += 256)
        Qst[(idx & 63) * PADT + (idx >> 6)] = Qc[idx];
    if (tid < 128)
        qmr[tid] = qmask[(r & 7) * 1024 + qt * 128 + tid];

    float oacc[8][4] = {};
    float rs[8] = {};

    for (int kt = 0; kt < 8; kt++) {
        __syncthreads();
        for (int idx = tid; idx < 8192; idx += 256)
            Kst[(idx & 63) * PADT + (idx >> 6)] = Kc[kt * 8192 + idx];
        for (int idx = tid; idx < 2048; idx += 256)
            ((float4*)Vs)[idx] = ((const float4*)(Vc + kt * 8192))[idx];
        if (tid < 128)
            kmr[tid] = kmask[(r & 7) * 1024 + kt * 128 + tid];
        __syncthreads();

        float s[8][8] = {};
        #pragma unroll 8
        for (int kk = 0; kk < 64; kk++) {
            float a[8], b[8];
            *(float4*)&a[0] = *(const float4*)&Qst[kk * PADT + ty * 8];
            *(float4*)&a[4] = *(const float4*)&Qst[kk * PADT + ty * 8 + 4];
            *(float4*)&b[0] = *(const float4*)&Kst[kk * PADT + tx * 8];
            *(float4*)&b[4] = *(const float4*)&Kst[kk * PADT + tx * 8 + 4];
            #pragma unroll
            for (int i = 0; i < 8; i++)
                #pragma unroll
                for (int j = 0; j < 8; j++)
                    s[i][j] = fmaf(a[i], b[j], s[i][j]);
        }

        #pragma unroll
        for (int i = 0; i < 8; i++) {
            float qm = qmr[ty * 8 + i];
            #pragma unroll
            for (int j = 0; j < 8; j++) {
                float p = (qm * kmr[tx * 8 + j] == 0.0f)
                              ? 0.0f : __expf(s[i][j] * 0.125f);
                rs[i] += p;
                s[i][j] = p;
            }
            *(float4*)&Ps[(ty * 8 + i) * 128 + tx * 8]     = *(float4*)&s[i][0];
            *(float4*)&Ps[(ty * 8 + i) * 128 + tx * 8 + 4] = *(float4*)&s[i][4];
        }
        __syncthreads();

        #pragma unroll 4
        for (int j = 0; j < 128; j++) {
            float4 bv = *(const float4*)&Vs[j * 64 + tx * 4];
            #pragma unroll
            for (int i = 0; i < 8; i++) {
                float a = Ps[(ty * 8 + i) * 128 + j];
                oacc[i][0] = fmaf(a, bv.x, oacc[i][0]);
                oacc[i][1] = fmaf(a, bv.y, oacc[i][1]);
                oacc[i][2] = fmaf(a, bv.z, oacc[i][2]);
                oacc[i][3] = fmaf(a, bv.w, oacc[i][3]);
            }
        }
    }

    float* Oc = g_ctx + (size_t)r * CHUNK_ELEMS + qt * 8192;
    #pragma unroll
    for (int i = 0; i < 8; i++) {
        float v = rs[i];
        v += __shfl_xor_sync(0xffffffffu, v, 1);
        v += __shfl_xor_sync(0xffffffffu, v, 2);
        v += __shfl_xor_sync(0xffffffffu, v, 4);
        v += __shfl_xor_sync(0xffffffffu, v, 8);
        float inv = 1.0f / fmaxf(v, 2e-15f);
        float4 o = make_float4(oacc[i][0] * inv, oacc[i][1] * inv,
                               oacc[i][2] * inv, oacc[i][3] * inv);
        *(float4*)&Oc[(ty * 8 + i) * 64 + tx * 4] = o;
    }
}

// ---------------------------------------------------------------------------
// Residual + LayerNorm (unchanged)
// ---------------------------------------------------------------------------
__global__ void __launch_bounds__(256) resid_ln_kernel(
    const float* __restrict__ resid, const float* __restrict__ gamma,
    const float* __restrict__ beta, float* __restrict__ out)
{
    __shared__ float red[8];
    __shared__ float bc;

    const int row = blockIdx.x;
    const int tid = threadIdx.x;
    const float* pr = g_proj + (size_t)row * 1024;
    const float* rr = resid + (size_t)row * 1024;

    float x[4];
    float sum = 0.0f;
    #pragma unroll
    for (int c = 0; c < 4; c++) {
        x[c] = rr[tid + 256 * c] + pr[tid + 256 * c];
        sum += x[c];
    }
    #pragma unroll
    for (int m = 16; m; m >>= 1) sum += __shfl_xor_sync(0xffffffffu, sum, m);
    if ((tid & 31) == 0) red[tid >> 5] = sum;
    __syncthreads();
    if (tid == 0) {
        float t = 0.0f;
        #pragma unroll
        for (int i = 0; i < 8; i++) t += red[i];
        bc = t;
    }
    __syncthreads();
    const float mean = bc * (1.0f / 1024.0f);

    float vs = 0.0f;
    #pragma unroll
    for (int c = 0; c < 4; c++) { float d = x[c] - mean; vs += d * d; }
    #pragma unroll
    for (int m = 16; m; m >>= 1) vs += __shfl_xor_sync(0xffffffffu, vs, m);
    __syncthreads();
    if ((tid & 31) == 0) red[tid >> 5] = vs;
    __syncthreads();
    if (tid == 0) {
        float t = 0.0f;
        #pragma unroll
        for (int i = 0; i < 8; i++) t += red[i];
        bc = t;
    }
    __syncthreads();
    const float var = bc * (1.0f / 1024.0f);
    const float inv = rsqrtf(var + 1e-5f);

    #pragma unroll
    for (int c = 0; c < 4; c++) {
        int idx = tid + 256 * c;
        out[(size_t)row * 1024 + idx] =
            (x[c] - mean) * inv * gamma[idx] + beta[idx];
    }
}

// ---------------------------------------------------------------------------
// Host launcher
// ---------------------------------------------------------------------------
extern "C" void kernel_launch(void* const* d_in, const int* in_sizes, int n_in,
                              void* d_out, int out_size)
{
    const float* query  = (const float*)d_in[0];
    const float* key    = (const float*)d_in[1];
    const float* value  = (const float*)d_in[2];
    const float* q_mask = (const float*)d_in[3];
    const float* k_mask = (const float*)d_in[4];
    const float* Wq     = (const float*)d_in[5];
    const float* bq     = (const float*)d_in[6];
    const float* Wk     = (const float*)d_in[7];
    const float* bk     = (const float*)d_in[8];
    const float* Wv     = (const float*)d_in[9];
    const float* bv     = (const float*)d_in[10];
    const float* Wo     = (const float*)d_in[11];
    const float* bo     = (const float*)d_in[12];
    const float* gamma  = (const float*)d_in[13];
    const float* beta   = (const float*)d_in[14];
    float* out = (float*)d_out;

    (void)in_sizes; (void)n_in; (void)out_size;

    cudaFuncSetAttribute(attn_kernel,
                         cudaFuncAttributeMaxDynamicSharedMemorySize,
                         ATTN_SMEM_BYTES);
    cudaFuncSetAttribute(gemm_mma_tf32,
                         cudaFuncAttributeMaxDynamicSharedMemorySize,
                         GT_SMEM_BYTES);

    float *gq, *gk, *gv, *gctx, *gproj;
    cudaGetSymbolAddress((void**)&gq,    g_q);
    cudaGetSymbolAddress((void**)&gk,    g_k);
    cudaGetSymbolAddress((void**)&gv,    g_v);
    cudaGetSymbolAddress((void**)&gctx,  g_ctx);
    cudaGetSymbolAddress((void**)&gproj, g_proj);

    dim3 ggrid(DIM / 128, M_ROWS / 128);   // (8, 64)

    gemm_mma_tf32<<<ggrid, 256, GT_SMEM_BYTES>>>(query, Wq, bq, gq);
    gemm_mma_tf32<<<ggrid, 256, GT_SMEM_BYTES>>>(key,   Wk, bk, gk);
    gemm_mma_tf32<<<ggrid, 256, GT_SMEM_BYTES>>>(value, Wv, bv, gv);

    attn_kernel<<<dim3(NCHUNK, 8), 256, ATTN_SMEM_BYTES>>>(q_mask, k_mask);

    gemm_mma_tf32<<<ggrid, 256, GT_SMEM_BYTES>>>(gctx, Wo, bo, gproj);

    resid_ln_kernel<<<M_ROWS, 256>>>(query, gamma, beta, out);
}

// round 5
// speedup vs baseline: 1.9771x; 1.3892x over previous
#include <cuda_runtime.h>
#include <cstdint>
#include <math.h>

// ---------------------------------------------------------------------------
// B=8, L=1024, D=1024, H=16, d=64.  M = 8192 token rows.
// GEMMs + attention via warp-level mma.sync tf32 (base sm_103 PTX).
// ---------------------------------------------------------------------------

#define M_ROWS  8192
#define DIM     1024
#define NCHUNK  128
#define CHUNK_ELEMS 65536

__device__ float g_q[M_ROWS * DIM];
__device__ float g_k[M_ROWS * DIM];
__device__ float g_v[M_ROWS * DIM];
__device__ float g_ctx[M_ROWS * DIM];
__device__ float g_proj[M_ROWS * DIM];

__device__ __forceinline__ uint32_t f2tf32(float x) {
    uint32_t u; asm("cvt.rna.tf32.f32 %0, %1;" : "=r"(u) : "f"(x)); return u;
}

__device__ __forceinline__ void mma_tf32(float* c, const uint32_t* a,
                                         const uint32_t* b) {
    asm volatile(
        "mma.sync.aligned.m16n8k8.row.col.f32.tf32.tf32.f32 "
        "{%0,%1,%2,%3}, {%4,%5,%6,%7}, {%8,%9}, {%0,%1,%2,%3};"
        : "+f"(c[0]), "+f"(c[1]), "+f"(c[2]), "+f"(c[3])
        : "r"(a[0]), "r"(a[1]), "r"(a[2]), "r"(a[3]), "r"(b[0]), "r"(b[1]));
}

// ---------------------------------------------------------------------------
// tf32 mma.sync GEMM: C = A @ W^T + bias.  CTA 128x128, K chunks of 16,
// 2 CTAs/SM.  Fragment-major smem (validated R4 conventions):
//  A (16x8 blk): lane=(m%8)*4+(k%4), frag=(m>=8)+2*(k>=4): blk=(MT*2+ks)*160,
//     off = blk + frag*40 + lane
//  B ( 8x8 blk): lane=(n%8)*4+(k%4), frag=(k>=4): blk=(NT*2+ks)*96,
//     off = blk + frag*48 + lane
// ---------------------------------------------------------------------------
#define ABLK 160
#define AFRG 40
#define BBLK 96
#define BFRG 48
#define ABUF (16 * ABLK)          // 2560 floats
#define BBUF (32 * BBLK)          // 3072 floats
#define GBUF (ABUF + BBUF)        // 5632
#define GT_SMEM_BYTES (2 * GBUF * 4)  // 45056

__global__ void __launch_bounds__(256, 2) gemm_mma_tf32(
    const float* __restrict__ A, const float* __restrict__ W,
    const float* __restrict__ bias, float* __restrict__ C)
{
    extern __shared__ float sm[];
    float* Abuf[2] = { sm, sm + GBUF };
    float* Bbuf[2] = { sm + ABUF, sm + GBUF + ABUF };

    const int tid  = threadIdx.x;
    const int lane = tid & 31;
    const int wid  = tid >> 5;
    const int wm   = wid & 1;
    const int wn   = wid >> 1;
    const int row0 = blockIdx.y * 128;
    const int col0 = blockIdx.x * 128;

    const int lrow = tid >> 1;
    const int h    = tid & 1;
    const float* Ap = A + (size_t)(row0 + lrow) * DIM + h * 4;
    const float* Wp = W + (size_t)(col0 + lrow) * DIM + h * 4;

    const int a_f0 = (lrow >> 3) & 1;
    const int a_rp = lrow & 7;
    const int a_MT = lrow >> 4;
    const int a_base = a_MT * 2 * ABLK + (a_f0 + 2 * h) * AFRG + a_rp * 4;
    const int b_n  = lrow & 7;
    const int b_NT = lrow >> 3;
    const int b_base = b_NT * 2 * BBLK + h * BFRG + b_n * 4;

    float4 ra[2], rb[2];
    #pragma unroll
    for (int j = 0; j < 2; j++) {
        ra[j] = *(const float4*)(Ap + j * 8);
        rb[j] = *(const float4*)(Wp + j * 8);
    }

    float acc[4][4][4];
    #pragma unroll
    for (int mt = 0; mt < 4; mt++)
        #pragma unroll
        for (int nt = 0; nt < 4; nt++)
            #pragma unroll
            for (int f = 0; f < 4; f++) acc[mt][nt][f] = 0.0f;

    #pragma unroll
    for (int j = 0; j < 2; j++) {
        float4 ua, ub;
        ua.x = __uint_as_float(f2tf32(ra[j].x));
        ua.y = __uint_as_float(f2tf32(ra[j].y));
        ua.z = __uint_as_float(f2tf32(ra[j].z));
        ua.w = __uint_as_float(f2tf32(ra[j].w));
        ub.x = __uint_as_float(f2tf32(rb[j].x));
        ub.y = __uint_as_float(f2tf32(rb[j].y));
        ub.z = __uint_as_float(f2tf32(rb[j].z));
        ub.w = __uint_as_float(f2tf32(rb[j].w));
        *(float4*)(Abuf[0] + a_base + j * ABLK) = ua;
        *(float4*)(Bbuf[0] + b_base + j * BBLK) = ub;
    }
    __syncthreads();

    for (int c = 0; c < 64; ++c) {
        const int cur = c & 1, nxt = cur ^ 1;
        if (c < 63) {
            const float* Ap2 = Ap + (c + 1) * 16;
            const float* Wp2 = Wp + (c + 1) * 16;
            #pragma unroll
            for (int j = 0; j < 2; j++) {
                ra[j] = *(const float4*)(Ap2 + j * 8);
                rb[j] = *(const float4*)(Wp2 + j * 8);
            }
        }

        const float* ab = Abuf[cur];
        const float* bb = Bbuf[cur];
        #pragma unroll
        for (int ks = 0; ks < 2; ks++) {
            uint32_t afr[4][4], bfr[4][2];
            #pragma unroll
            for (int mt = 0; mt < 4; mt++) {
                const float* p = ab + ((wm * 4 + mt) * 2 + ks) * ABLK + lane;
                #pragma unroll
                for (int f = 0; f < 4; f++)
                    afr[mt][f] = __float_as_uint(p[f * AFRG]);
            }
            #pragma unroll
            for (int nt = 0; nt < 4; nt++) {
                const float* p = bb + ((wn * 4 + nt) * 2 + ks) * BBLK + lane;
                #pragma unroll
                for (int f = 0; f < 2; f++)
                    bfr[nt][f] = __float_as_uint(p[f * BFRG]);
            }
            #pragma unroll
            for (int mt = 0; mt < 4; mt++)
                #pragma unroll
                for (int nt = 0; nt < 4; nt++)
                    mma_tf32(acc[mt][nt], afr[mt], bfr[nt]);
        }

        if (c < 63) {
            #pragma unroll
            for (int j = 0; j < 2; j++) {
                float4 ua, ub;
                ua.x = __uint_as_float(f2tf32(ra[j].x));
                ua.y = __uint_as_float(f2tf32(ra[j].y));
                ua.z = __uint_as_float(f2tf32(ra[j].z));
                ua.w = __uint_as_float(f2tf32(ra[j].w));
                ub.x = __uint_as_float(f2tf32(rb[j].x));
                ub.y = __uint_as_float(f2tf32(rb[j].y));
                ub.z = __uint_as_float(f2tf32(rb[j].z));
                ub.w = __uint_as_float(f2tf32(rb[j].w));
                *(float4*)(Abuf[nxt] + a_base + j * ABLK) = ua;
                *(float4*)(Bbuf[nxt] + b_base + j * BBLK) = ub;
            }
        }
        __syncthreads();
    }

    const int qr = lane >> 2;
    const int qc = (lane & 3) * 2;
    #pragma unroll
    for (int nt = 0; nt < 4; nt++) {
        const int cc = col0 + wn * 32 + nt * 8 + qc;
        const float b0 = bias[cc], b1 = bias[cc + 1];
        #pragma unroll
        for (int mt = 0; mt < 4; mt++) {
            const int rr = row0 + wm * 64 + mt * 16 + qr;
            float2 o0 = make_float2(acc[mt][nt][0] + b0, acc[mt][nt][1] + b1);
            float2 o1 = make_float2(acc[mt][nt][2] + b0, acc[mt][nt][3] + b1);
            *(float2*)(C + (size_t)rr * DIM + cc)       = o0;
            *(float2*)(C + (size_t)(rr + 8) * DIM + cc) = o1;
        }
    }
}

// ---------------------------------------------------------------------------
// Attention via mma.sync tf32.  CTA = chunk r x 128-q tile.  Warps 2(m)x4(n).
// Per k-tile (128 keys):  S = Q K^T (mma) -> mask/exp -> P smem -> O += P V.
// Smem (lane-contiguous fragment layouts; conventions as GEMM):
//   Qs: A-frag, blocks (MT0..7, ks0..7)*128:  off = blk + lane*4 + reg
//   Ks: B-frag (n=key), blocks (NT0..15, ks0..7)*64: off = blk + lane*2 + reg
//   Vs: B-frag (n=d, k=key), blocks (NT0..7, ks0..15)*64: off = blk + lane*2 + reg
//   Ps: row-major [128][132] fp32 (tf32-rounded) — all frag loads bank-clean
// ---------------------------------------------------------------------------
#define ATT_SMEM_FLOATS (8192 + 8192 + 8192 + 128*132 + 128 + 128 + 128)
#define ATT_SMEM_BYTES  (ATT_SMEM_FLOATS * 4)   // 167424

__global__ void __launch_bounds__(256) attn_mma_kernel(
    const float* __restrict__ qmask, const float* __restrict__ kmask)
{
    extern __shared__ float sm[];
    float* Qs  = sm;
    float* Ks  = sm + 8192;
    float* Vs  = sm + 16384;
    float* Ps  = sm + 24576;            // 128*132 = 16896
    float* qmr = sm + 24576 + 16896;    // 41472
    float* kmr = qmr + 128;
    float* rowsum = kmr + 128;

    const int tid  = threadIdx.x;
    const int lane = tid & 31;
    const int wid  = tid >> 5;
    const int wm   = wid & 1;
    const int wn   = wid >> 1;
    const int r    = blockIdx.x;
    const int qt   = blockIdx.y;

    const float* Qc = g_q + (size_t)r * CHUNK_ELEMS + qt * 8192;
    const float* Kc = g_k + (size_t)r * CHUNK_ELEMS;
    const float* Vc = g_v + (size_t)r * CHUNK_ELEMS;

    // ---- Q -> A-frag smem (once) ----
    {
        const int q  = tid >> 1;
        const int hh = tid & 1;
        const int MT = q >> 4;
        const int fb = ((q & 15) >= 8) ? 1 : 0;
        const int lb = (q & 7) * 4;
        #pragma unroll
        for (int j = 0; j < 8; j++) {
            const int d0 = hh * 32 + j * 4;
            float4 v = *(const float4*)(Qc + q * 64 + d0);
            const int ks  = d0 >> 3;
            const int reg = fb + (((d0 & 7) >= 4) ? 2 : 0);
            float* dst = Qs + (MT * 8 + ks) * 128 + reg;
            dst[(lb + 0) * 4] = __uint_as_float(f2tf32(v.x));
            dst[(lb + 1) * 4] = __uint_as_float(f2tf32(v.y));
            dst[(lb + 2) * 4] = __uint_as_float(f2tf32(v.z));
            dst[(lb + 3) * 4] = __uint_as_float(f2tf32(v.w));
        }
    }
    if (tid < 128) {
        qmr[tid] = qmask[(r & 7) * 1024 + qt * 128 + tid];
        rowsum[tid] = 0.0f;
    }

    float oacc[4][2][4];
    #pragma unroll
    for (int mt = 0; mt < 4; mt++)
        #pragma unroll
        for (int n2 = 0; n2 < 2; n2++)
            #pragma unroll
            for (int f = 0; f < 4; f++) oacc[mt][n2][f] = 0.0f;
    float rs0[4] = {0, 0, 0, 0}, rs1[4] = {0, 0, 0, 0};

    for (int kt = 0; kt < 8; kt++) {
        __syncthreads();   // prev PV done; Ks/Vs/Ps free (Qs ready on iter 0)
        {
            const int key = tid >> 1;
            const int hh  = tid & 1;
            const int NT  = key >> 3;
            const int lb  = (key & 7) * 4;
            const int ksv = key >> 3;                    // V: k-block of key
            const int regv = ((key & 7) >= 4) ? 1 : 0;
            const int klo = key & 3;
            #pragma unroll
            for (int j = 0; j < 8; j++) {
                const int d0 = hh * 32 + j * 4;
                float4 kv = *(const float4*)(Kc + kt * 8192 + key * 64 + d0);
                float4 vv = *(const float4*)(Vc + kt * 8192 + key * 64 + d0);
                const int ks  = d0 >> 3;
                const int reg = ((d0 & 7) >= 4) ? 1 : 0;
                float* dk = Ks + (NT * 8 + ks) * 64 + reg;
                dk[(lb + 0) * 2] = __uint_as_float(f2tf32(kv.x));
                dk[(lb + 1) * 2] = __uint_as_float(f2tf32(kv.y));
                dk[(lb + 2) * 2] = __uint_as_float(f2tf32(kv.z));
                dk[(lb + 3) * 2] = __uint_as_float(f2tf32(kv.w));
                const int NTv = d0 >> 3;
                const int lv  = (d0 & 7) * 4 + klo;
                float* dv = Vs + (NTv * 16 + ksv) * 64 + regv;
                dv[(lv + 0)  * 2] = __uint_as_float(f2tf32(vv.x));
                dv[(lv + 4)  * 2] = __uint_as_float(f2tf32(vv.y));
                dv[(lv + 8)  * 2] = __uint_as_float(f2tf32(vv.z));
                dv[(lv + 12) * 2] = __uint_as_float(f2tf32(vv.w));
            }
        }
        if (tid < 128)
            kmr[tid] = kmask[(r & 7) * 1024 + kt * 128 + tid];
        __syncthreads();

        // ---- S = Q @ K^T ----
        float sacc[4][4][4];
        #pragma unroll
        for (int mt = 0; mt < 4; mt++)
            #pragma unroll
            for (int nt = 0; nt < 4; nt++)
                #pragma unroll
                for (int f = 0; f < 4; f++) sacc[mt][nt][f] = 0.0f;

        #pragma unroll
        for (int ks = 0; ks < 8; ks++) {
            uint32_t afr[4][4], bfr[4][2];
            #pragma unroll
            for (int mt = 0; mt < 4; mt++) {
                float4 qv = *(const float4*)(Qs + ((wm * 4 + mt) * 8 + ks) * 128 + lane * 4);
                afr[mt][0] = __float_as_uint(qv.x);
                afr[mt][1] = __float_as_uint(qv.y);
                afr[mt][2] = __float_as_uint(qv.z);
                afr[mt][3] = __float_as_uint(qv.w);
            }
            #pragma unroll
            for (int nt = 0; nt < 4; nt++) {
                float2 kv = *(const float2*)(Ks + ((wn * 4 + nt) * 8 + ks) * 64 + lane * 2);
                bfr[nt][0] = __float_as_uint(kv.x);
                bfr[nt][1] = __float_as_uint(kv.y);
            }
            #pragma unroll
            for (int mt = 0; mt < 4; mt++)
                #pragma unroll
                for (int nt = 0; nt < 4; nt++)
                    mma_tf32(sacc[mt][nt], afr[mt], bfr[nt]);
        }

        // ---- P = mask ? exp(S/8) : 0 ; spill to Ps; accumulate row sums ----
        {
            float km0[4], km1[4], qm0[4], qm1[4];
            #pragma unroll
            for (int nt = 0; nt < 4; nt++) {
                km0[nt] = kmr[wn * 32 + nt * 8 + 2 * (lane & 3)];
                km1[nt] = kmr[wn * 32 + nt * 8 + 2 * (lane & 3) + 1];
            }
            #pragma unroll
            for (int mt = 0; mt < 4; mt++) {
                qm0[mt] = qmr[wm * 64 + mt * 16 + (lane >> 2)];
                qm1[mt] = qmr[wm * 64 + mt * 16 + (lane >> 2) + 8];
            }
            #pragma unroll
            for (int mt = 0; mt < 4; mt++) {
                const int row = wm * 64 + mt * 16 + (lane >> 2);
                #pragma unroll
                for (int nt = 0; nt < 4; nt++) {
                    const int col = wn * 32 + nt * 8 + 2 * (lane & 3);
                    float p0 = (qm0[mt] * km0[nt] == 0.0f) ? 0.0f
                        : __uint_as_float(f2tf32(__expf(sacc[mt][nt][0] * 0.125f)));
                    float p1 = (qm0[mt] * km1[nt] == 0.0f) ? 0.0f
                        : __uint_as_float(f2tf32(__expf(sacc[mt][nt][1] * 0.125f)));
                    float p2 = (qm1[mt] * km0[nt] == 0.0f) ? 0.0f
                        : __uint_as_float(f2tf32(__expf(sacc[mt][nt][2] * 0.125f)));
                    float p3 = (qm1[mt] * km1[nt] == 0.0f) ? 0.0f
                        : __uint_as_float(f2tf32(__expf(sacc[mt][nt][3] * 0.125f)));
                    rs0[mt] += p0 + p1;
                    rs1[mt] += p2 + p3;
                    *(float2*)&Ps[row * 132 + col]       = make_float2(p0, p1);
                    *(float2*)&Ps[(row + 8) * 132 + col] = make_float2(p2, p3);
                }
            }
        }
        __syncthreads();

        // ---- O += P @ V ----
        #pragma unroll
        for (int k2 = 0; k2 < 16; k2++) {
            uint32_t pfr[4][4], vfr[2][2];
            #pragma unroll
            for (int mt = 0; mt < 4; mt++) {
                const float* pp = Ps + (wm * 64 + mt * 16 + (lane >> 2)) * 132
                                  + k2 * 8 + (lane & 3);
                pfr[mt][0] = __float_as_uint(pp[0]);
                pfr[mt][1] = __float_as_uint(pp[8 * 132]);
                pfr[mt][2] = __float_as_uint(pp[4]);
                pfr[mt][3] = __float_as_uint(pp[8 * 132 + 4]);
            }
            #pragma unroll
            for (int n2 = 0; n2 < 2; n2++) {
                float2 vv = *(const float2*)(Vs + ((wn * 2 + n2) * 16 + k2) * 64 + lane * 2);
                vfr[n2][0] = __float_as_uint(vv.x);
                vfr[n2][1] = __float_as_uint(vv.y);
            }
            #pragma unroll
            for (int mt = 0; mt < 4; mt++)
                #pragma unroll
                for (int n2 = 0; n2 < 2; n2++)
                    mma_tf32(oacc[mt][n2], pfr[mt], vfr[n2]);
        }
    }

    // ---- row-sum reduction (quad shuffles + cross-warp smem atomics) ----
    #pragma unroll
    for (int mt = 0; mt < 4; mt++) {
        float v0 = rs0[mt], v1 = rs1[mt];
        v0 += __shfl_xor_sync(0xffffffffu, v0, 1);
        v0 += __shfl_xor_sync(0xffffffffu, v0, 2);
        v1 += __shfl_xor_sync(0xffffffffu, v1, 1);
        v1 += __shfl_xor_sync(0xffffffffu, v1, 2);
        if ((lane & 3) == 0) {
            atomicAdd(&rowsum[wm * 64 + mt * 16 + (lane >> 2)], v0);
            atomicAdd(&rowsum[wm * 64 + mt * 16 + (lane >> 2) + 8], v1);
        }
    }
    __syncthreads();

    // ---- normalize + store ----
    float* Oc = g_ctx + (size_t)r * CHUNK_ELEMS + qt * 8192;
    #pragma unroll
    for (int mt = 0; mt < 4; mt++) {
        const int row = wm * 64 + mt * 16 + (lane >> 2);
        const float inv0 = 1.0f / fmaxf(rowsum[row], 2e-15f);
        const float inv1 = 1.0f / fmaxf(rowsum[row + 8], 2e-15f);
        #pragma unroll
        for (int n2 = 0; n2 < 2; n2++) {
            const int col = wn * 16 + n2 * 8 + 2 * (lane & 3);
            float2 o0 = make_float2(oacc[mt][n2][0] * inv0, oacc[mt][n2][1] * inv0);
            float2 o1 = make_float2(oacc[mt][n2][2] * inv1, oacc[mt][n2][3] * inv1);
            *(float2*)&Oc[row * 64 + col]       = o0;
            *(float2*)&Oc[(row + 8) * 64 + col] = o1;
        }
    }
}

// ---------------------------------------------------------------------------
// Residual + LayerNorm (unchanged)
// ---------------------------------------------------------------------------
__global__ void __launch_bounds__(256) resid_ln_kernel(
    const float* __restrict__ resid, const float* __restrict__ gamma,
    const float* __restrict__ beta, float* __restrict__ out)
{
    __shared__ float red[8];
    __shared__ float bc;

    const int row = blockIdx.x;
    const int tid = threadIdx.x;
    const float* pr = g_proj + (size_t)row * 1024;
    const float* rr = resid + (size_t)row * 1024;

    float x[4];
    float sum = 0.0f;
    #pragma unroll
    for (int c = 0; c < 4; c++) {
        x[c] = rr[tid + 256 * c] + pr[tid + 256 * c];
        sum += x[c];
    }
    #pragma unroll
    for (int m = 16; m; m >>= 1) sum += __shfl_xor_sync(0xffffffffu, sum, m);
    if ((tid & 31) == 0) red[tid >> 5] = sum;
    __syncthreads();
    if (tid == 0) {
        float t = 0.0f;
        #pragma unroll
        for (int i = 0; i < 8; i++) t += red[i];
        bc = t;
    }
    __syncthreads();
    const float mean = bc * (1.0f / 1024.0f);

    float vs = 0.0f;
    #pragma unroll
    for (int c = 0; c < 4; c++) { float d = x[c] - mean; vs += d * d; }
    #pragma unroll
    for (int m = 16; m; m >>= 1) vs += __shfl_xor_sync(0xffffffffu, vs, m);
    __syncthreads();
    if ((tid & 31) == 0) red[tid >> 5] = vs;
    __syncthreads();
    if (tid == 0) {
        float t = 0.0f;
        #pragma unroll
        for (int i = 0; i < 8; i++) t += red[i];
        bc = t;
    }
    __syncthreads();
    const float var = bc * (1.0f / 1024.0f);
    const float inv = rsqrtf(var + 1e-5f);

    #pragma unroll
    for (int c = 0; c < 4; c++) {
        int idx = tid + 256 * c;
        out[(size_t)row * 1024 + idx] =
            (x[c] - mean) * inv * gamma[idx] + beta[idx];
    }
}

// ---------------------------------------------------------------------------
// Host launcher
// ---------------------------------------------------------------------------
extern "C" void kernel_launch(void* const* d_in, const int* in_sizes, int n_in,
                              void* d_out, int out_size)
{
    const float* query  = (const float*)d_in[0];
    const float* key    = (const float*)d_in[1];
    const float* value  = (const float*)d_in[2];
    const float* q_mask = (const float*)d_in[3];
    const float* k_mask = (const float*)d_in[4];
    const float* Wq     = (const float*)d_in[5];
    const float* bq     = (const float*)d_in[6];
    const float* Wk     = (const float*)d_in[7];
    const float* bk     = (const float*)d_in[8];
    const float* Wv     = (const float*)d_in[9];
    const float* bv     = (const float*)d_in[10];
    const float* Wo     = (const float*)d_in[11];
    const float* bo     = (const float*)d_in[12];
    const float* gamma  = (const float*)d_in[13];
    const float* beta   = (const float*)d_in[14];
    float* out = (float*)d_out;

    (void)in_sizes; (void)n_in; (void)out_size;

    cudaFuncSetAttribute(attn_mma_kernel,
                         cudaFuncAttributeMaxDynamicSharedMemorySize,
                         ATT_SMEM_BYTES);
    cudaFuncSetAttribute(gemm_mma_tf32,
                         cudaFuncAttributeMaxDynamicSharedMemorySize,
                         GT_SMEM_BYTES);

    float *gq, *gk, *gv, *gctx, *gproj;
    cudaGetSymbolAddress((void**)&gq,    g_q);
    cudaGetSymbolAddress((void**)&gk,    g_k);
    cudaGetSymbolAddress((void**)&gv,    g_v);
    cudaGetSymbolAddress((void**)&gctx,  g_ctx);
    cudaGetSymbolAddress((void**)&gproj, g_proj);

    dim3 ggrid(DIM / 128, M_ROWS / 128);   // (8, 64)

    gemm_mma_tf32<<<ggrid, 256, GT_SMEM_BYTES>>>(query, Wq, bq, gq);
    gemm_mma_tf32<<<ggrid, 256, GT_SMEM_BYTES>>>(key,   Wk, bk, gk);
    gemm_mma_tf32<<<ggrid, 256, GT_SMEM_BYTES>>>(value, Wv, bv, gv);

    attn_mma_kernel<<<dim3(NCHUNK, 8), 256, ATT_SMEM_BYTES>>>(q_mask, k_mask);

    gemm_mma_tf32<<<ggrid, 256, GT_SMEM_BYTES>>>(gctx, Wo, bo, gproj);

    resid_ln_kernel<<<M_ROWS, 256>>>(query, gamma, beta, out);
}

// round 6
// speedup vs baseline: 2.3623x; 1.1948x over previous
#include <cuda_runtime.h>
#include <cuda_bf16.h>
#include <cstdint>
#include <math.h>

// ---------------------------------------------------------------------------
// B=8, L=1024, D=1024, H=16, d=64.  M = 8192 token rows.
// All GEMMs + attention via warp-level mma.sync bf16 m16n8k16 (fp32 accum).
// ---------------------------------------------------------------------------

#define M_ROWS  8192
#define DIM     1024
#define NCHUNK  128
#define CHUNK_ELEMS 65536

__device__ float g_q[M_ROWS * DIM];
__device__ float g_k[M_ROWS * DIM];
__device__ float g_v[M_ROWS * DIM];
__device__ float g_ctx[M_ROWS * DIM];
__device__ float g_proj[M_ROWS * DIM];

__device__ __forceinline__ uint32_t packbf(float a, float b) {
    __nv_bfloat162 t = __floats2bfloat162_rn(a, b);
    return *reinterpret_cast<uint32_t*>(&t);
}

__device__ __forceinline__ void mma_bf16(float* c, const uint32_t* a,
                                         const uint32_t* b) {
    asm volatile(
        "mma.sync.aligned.m16n8k16.row.col.f32.bf16.bf16.f32 "
        "{%0,%1,%2,%3}, {%4,%5,%6,%7}, {%8,%9}, {%0,%1,%2,%3};"
        : "+f"(c[0]), "+f"(c[1]), "+f"(c[2]), "+f"(c[3])
        : "r"(a[0]), "r"(a[1]), "r"(a[2]), "r"(a[3]), "r"(b[0]), "r"(b[1]));
}

// Fragment smem conventions (packed bf16 pairs, 1 word = 2 consecutive k):
//  A 16x16 block: word(m, p) at reg*36 + (m%8)*4 + p%4, reg = (m%16>=8)+2*(p>=4)
//  B  8x16 block: word(n, p) at reg*36 + (n%8)*4 + p%4, reg = (p>=4)
//  (p = k-pair index 0..7; low half of word = even k)

// ---------------------------------------------------------------------------
// bf16 GEMM: C[8192,1024] = A @ W^T + bias.  CTA 128x128, 256 thr,
// warps 2(m)x4(n), warp tile 64x32, K chunks of 32 (2 k16 steps), 2 CTAs/SM.
// A blocks (MT0..7, ks0..1)*160 words; B blocks (NT0..15, ks0..1)*80 words.
// ---------------------------------------------------------------------------
#define G_ABUF 2560
#define G_BBUF 2560
#define G_BUF  (G_ABUF + G_BBUF)            // 5120 words
#define GT_SMEM_BYTES (2 * G_BUF * 4)       // 40960

__global__ void __launch_bounds__(256, 2) gemm_bf16(
    const float* __restrict__ A, const float* __restrict__ W,
    const float* __restrict__ bias, float* __restrict__ C)
{
    extern __shared__ uint32_t smg[];
    uint32_t* Abuf[2] = { smg, smg + G_BUF };
    uint32_t* Bbuf[2] = { smg + G_ABUF, smg + G_BUF + G_ABUF };

    const int tid  = threadIdx.x;
    const int lane = tid & 31;
    const int wid  = tid >> 5;
    const int wm   = wid & 1;
    const int wn   = wid >> 1;
    const int row0 = blockIdx.y * 128;
    const int col0 = blockIdx.x * 128;

    const int m = tid & 127;        // loader row
    const int h = tid >> 7;         // k-half (16 k each)
    const float* Ap = A + (size_t)(row0 + m) * DIM + h * 16;
    const float* Wp = W + (size_t)(col0 + m) * DIM + h * 16;

    const int abase = ((m >> 4) * 2 + h) * 160 + ((m >> 3) & 1) * 36 + (m & 7) * 4;
    const int bbase = ((m >> 3) * 2 + h) * 80 + (m & 7) * 4;

    uint32_t wa[8], wb[8];
    #pragma unroll
    for (int j = 0; j < 4; j++) {
        float4 va = *(const float4*)(Ap + j * 4);
        float4 vb = *(const float4*)(Wp + j * 4);
        wa[j * 2 + 0] = packbf(va.x, va.y);
        wa[j * 2 + 1] = packbf(va.z, va.w);
        wb[j * 2 + 0] = packbf(vb.x, vb.y);
        wb[j * 2 + 1] = packbf(vb.z, vb.w);
    }

    float acc[4][4][4];
    #pragma unroll
    for (int mt = 0; mt < 4; mt++)
        #pragma unroll
        for (int nt = 0; nt < 4; nt++)
            #pragma unroll
            for (int f = 0; f < 4; f++) acc[mt][nt][f] = 0.0f;

    *(uint4*)(Abuf[0] + abase)      = *(uint4*)&wa[0];
    *(uint4*)(Abuf[0] + abase + 72) = *(uint4*)&wa[4];
    *(uint4*)(Bbuf[0] + bbase)      = *(uint4*)&wb[0];
    *(uint4*)(Bbuf[0] + bbase + 36) = *(uint4*)&wb[4];
    __syncthreads();

    for (int c = 0; c < 32; ++c) {
        const int cur = c & 1, nxt = cur ^ 1;
        if (c < 31) {
            const float* Ap2 = Ap + (c + 1) * 32;
            const float* Wp2 = Wp + (c + 1) * 32;
            #pragma unroll
            for (int j = 0; j < 4; j++) {
                float4 va = *(const float4*)(Ap2 + j * 4);
                float4 vb = *(const float4*)(Wp2 + j * 4);
                wa[j * 2 + 0] = packbf(va.x, va.y);
                wa[j * 2 + 1] = packbf(va.z, va.w);
                wb[j * 2 + 0] = packbf(vb.x, vb.y);
                wb[j * 2 + 1] = packbf(vb.z, vb.w);
            }
        }

        const uint32_t* ab = Abuf[cur];
        const uint32_t* bb = Bbuf[cur];
        #pragma unroll
        for (int ks = 0; ks < 2; ks++) {
            uint32_t af[4][4], bf_[4][2];
            #pragma unroll
            for (int mt = 0; mt < 4; mt++) {
                const uint32_t* p = ab + ((wm * 4 + mt) * 2 + ks) * 160 + lane;
                #pragma unroll
                for (int f = 0; f < 4; f++) af[mt][f] = p[f * 36];
            }
            #pragma unroll
            for (int nt = 0; nt < 4; nt++) {
                const uint32_t* p = bb + ((wn * 4 + nt) * 2 + ks) * 80 + lane;
                bf_[nt][0] = p[0];
                bf_[nt][1] = p[36];
            }
            #pragma unroll
            for (int mt = 0; mt < 4; mt++)
                #pragma unroll
                for (int nt = 0; nt < 4; nt++)
                    mma_bf16(acc[mt][nt], af[mt], bf_[nt]);
        }

        if (c < 31) {
            *(uint4*)(Abuf[nxt] + abase)      = *(uint4*)&wa[0];
            *(uint4*)(Abuf[nxt] + abase + 72) = *(uint4*)&wa[4];
            *(uint4*)(Bbuf[nxt] + bbase)      = *(uint4*)&wb[0];
            *(uint4*)(Bbuf[nxt] + bbase + 36) = *(uint4*)&wb[4];
        }
        __syncthreads();
    }

    const int qr = lane >> 2;
    const int qc = (lane & 3) * 2;
    #pragma unroll
    for (int nt = 0; nt < 4; nt++) {
        const int cc = col0 + wn * 32 + nt * 8 + qc;
        const float b0 = bias[cc], b1 = bias[cc + 1];
        #pragma unroll
        for (int mt = 0; mt < 4; mt++) {
            const int rr = row0 + wm * 64 + mt * 16 + qr;
            float2 o0 = make_float2(acc[mt][nt][0] + b0, acc[mt][nt][1] + b1);
            float2 o1 = make_float2(acc[mt][nt][2] + b0, acc[mt][nt][3] + b1);
            *(float2*)(C + (size_t)rr * DIM + cc)       = o0;
            *(float2*)(C + (size_t)(rr + 8) * DIM + cc) = o1;
        }
    }
}

// ---------------------------------------------------------------------------
// Attention, bf16 mma.  CTA = 512 thr (16 warps, 4m x 4n), chunk r x 128 q rows.
// Per k-tile (128 keys): S = Q K^T -> mask/exp (regs) -> P packed bf16 smem ->
// O += P V.  Rowsums from bf16-rounded P, reduced at the end.
// Smem words: Qs 5120 | Ks 5120 | Vs 5632 | Ps 8704 | qmr/kmr/rowsum 384
// ---------------------------------------------------------------------------
#define AT_QS 0
#define AT_KS 5120
#define AT_VS 10240
#define AT_PS 15872
#define AT_QM 24576
#define AT_KM 24704
#define AT_RS 24832
#define AT_WORDS 24960
#define AT_SMEM_BYTES (AT_WORDS * 4)   // 99840

__global__ void __launch_bounds__(512) attn_bf16_kernel(
    const float* __restrict__ qmask, const float* __restrict__ kmask)
{
    extern __shared__ uint32_t smw[];
    uint32_t* Qs = smw + AT_QS;
    uint32_t* Ks = smw + AT_KS;
    uint32_t* Vs = smw + AT_VS;
    uint32_t* Ps = smw + AT_PS;
    float* qmr    = (float*)(smw + AT_QM);
    float* kmr    = (float*)(smw + AT_KM);
    float* rowsum = (float*)(smw + AT_RS);

    const int tid  = threadIdx.x;
    const int lane = tid & 31;
    const int wid  = tid >> 5;
    const int wm   = wid & 3;     // row group of 32
    const int wn   = wid >> 2;    // S: key group of 32 ; PV: d group of 16
    const int r    = blockIdx.x;
    const int qt   = blockIdx.y;

    const float* Qc = g_q + (size_t)r * CHUNK_ELEMS + qt * 8192;
    const float* Kc = g_k + (size_t)r * CHUNK_ELEMS;
    const float* Vc = g_v + (size_t)r * CHUNK_ELEMS;

    // ---- Q -> A-frag smem (once).  thread: row m=tid&127, ks=tid>>7 ----
    {
        const int m  = tid & 127;
        const int kq = tid >> 7;          // 0..3
        const float* src = Qc + m * 64 + kq * 16;
        uint32_t w[8];
        #pragma unroll
        for (int j = 0; j < 4; j++) {
            float4 v = *(const float4*)(src + j * 4);
            w[j * 2 + 0] = packbf(v.x, v.y);
            w[j * 2 + 1] = packbf(v.z, v.w);
        }
        const int base = ((m >> 4) * 4 + kq) * 160 + ((m >> 3) & 1) * 36 + (m & 7) * 4;
        *(uint4*)(Qs + base)      = *(uint4*)&w[0];
        *(uint4*)(Qs + base + 72) = *(uint4*)&w[4];
    }
    if (tid < 128) {
        qmr[tid] = qmask[(r & 7) * 1024 + qt * 128 + tid];
        rowsum[tid] = 0.0f;
    }

    float oacc[2][2][4];
    #pragma unroll
    for (int mt = 0; mt < 2; mt++)
        #pragma unroll
        for (int nd = 0; nd < 2; nd++)
            #pragma unroll
            for (int f = 0; f < 4; f++) oacc[mt][nd][f] = 0.0f;
    float rs0[2] = {0, 0}, rs1[2] = {0, 0};

    for (int kt = 0; kt < 8; kt++) {
        __syncthreads();   // K/V/Ps consumers of prev iter done (Qs ready @0)

        // ---- K loader: B-frag (n=key, k=d).  blocks (NT0..15, ks0..3)*80 ----
        {
            const int key = tid & 127;
            const int kq  = tid >> 7;
            const float* src = Kc + kt * 8192 + key * 64 + kq * 16;
            uint32_t w[8];
            #pragma unroll
            for (int j = 0; j < 4; j++) {
                float4 v = *(const float4*)(src + j * 4);
                w[j * 2 + 0] = packbf(v.x, v.y);
                w[j * 2 + 1] = packbf(v.z, v.w);
            }
            const int base = ((key >> 3) * 4 + kq) * 80 + (key & 7) * 4;
            *(uint4*)(Ks + base)      = *(uint4*)&w[0];
            *(uint4*)(Ks + base + 36) = *(uint4*)&w[4];
        }
        // ---- V loader: B-frag (n=d, k=key pairs). blocks (NTd0..7, ksv0..7)*88 ----
        {
            const int kp = tid & 63;     // key pair
            const int dg = tid >> 6;     // d octet 0..7
            const float* s0 = Vc + kt * 8192 + (2 * kp) * 64 + dg * 8;
            const float* s1 = s0 + 64;
            float4 a0 = *(const float4*)(s0);
            float4 a1 = *(const float4*)(s0 + 4);
            float4 b0 = *(const float4*)(s1);
            float4 b1 = *(const float4*)(s1 + 4);
            uint32_t w[8];
            w[0] = packbf(a0.x, b0.x); w[1] = packbf(a0.y, b0.y);
            w[2] = packbf(a0.z, b0.z); w[3] = packbf(a0.w, b0.w);
            w[4] = packbf(a1.x, b1.x); w[5] = packbf(a1.y, b1.y);
            w[6] = packbf(a1.z, b1.z); w[7] = packbf(a1.w, b1.w);
            const int p = kp & 7;
            const int base = (dg * 8 + (kp >> 3)) * 88 + (p >> 2) * 36 + (p & 3);
            #pragma unroll
            for (int i = 0; i < 8; i++) Vs[base + i * 4] = w[i];
        }
        if (tid < 128)
            kmr[tid] = kmask[(r & 7) * 1024 + kt * 128 + tid];
        __syncthreads();

        // ---- S = Q K^T : warp rows wm*32 (2 m16), keys wn*32 (4 n8) ----
        float sacc[2][4][4];
        #pragma unroll
        for (int mt = 0; mt < 2; mt++)
            #pragma unroll
            for (int nt = 0; nt < 4; nt++)
                #pragma unroll
                for (int f = 0; f < 4; f++) sacc[mt][nt][f] = 0.0f;

        #pragma unroll
        for (int ks = 0; ks < 4; ks++) {
            uint32_t af[2][4], bf_[4][2];
            #pragma unroll
            for (int mt = 0; mt < 2; mt++) {
                const uint32_t* p = Qs + ((wm * 2 + mt) * 4 + ks) * 160 + lane;
                #pragma unroll
                for (int f = 0; f < 4; f++) af[mt][f] = p[f * 36];
            }
            #pragma unroll
            for (int nt = 0; nt < 4; nt++) {
                const uint32_t* p = Ks + ((wn * 4 + nt) * 4 + ks) * 80 + lane;
                bf_[nt][0] = p[0];
                bf_[nt][1] = p[36];
            }
            #pragma unroll
            for (int mt = 0; mt < 2; mt++)
                #pragma unroll
                for (int nt = 0; nt < 4; nt++)
                    mma_bf16(sacc[mt][nt], af[mt], bf_[nt]);
        }

        // ---- P = mask ? exp(S/8) : 0 ; pack to Ps; rowsums (bf16-rounded) ----
        #pragma unroll
        for (int mt = 0; mt < 2; mt++) {
            const int row = wm * 32 + mt * 16 + (lane >> 2);
            const float qm0 = qmr[row], qm1 = qmr[row + 8];
            #pragma unroll
            for (int nt = 0; nt < 4; nt++) {
                const int colp = wn * 16 + nt * 4 + (lane & 3);   // key pair
                const float km0 = kmr[2 * colp], km1 = kmr[2 * colp + 1];
                float p0 = (qm0 * km0 == 0.0f) ? 0.0f : __expf(sacc[mt][nt][0] * 0.125f);
                float p1 = (qm0 * km1 == 0.0f) ? 0.0f : __expf(sacc[mt][nt][1] * 0.125f);
                float p2 = (qm1 * km0 == 0.0f) ? 0.0f : __expf(sacc[mt][nt][2] * 0.125f);
                float p3 = (qm1 * km1 == 0.0f) ? 0.0f : __expf(sacc[mt][nt][3] * 0.125f);
                uint32_t w0 = packbf(p0, p1);
                uint32_t w1 = packbf(p2, p3);
                float2 f0 = __bfloat1622float2(*(__nv_bfloat162*)&w0);
                float2 f1 = __bfloat1622float2(*(__nv_bfloat162*)&w1);
                rs0[mt] += f0.x + f0.y;
                rs1[mt] += f1.x + f1.y;
                Ps[row * 68 + colp]       = w0;
                Ps[(row + 8) * 68 + colp] = w1;
            }
        }
        __syncthreads();

        // ---- O += P V : warp rows wm*32, d cols wn*16 (2 n8), k = 128 keys ----
        #pragma unroll
        for (int kb = 0; kb < 8; kb++) {
            uint32_t pa[2][4], vb[2][2];
            #pragma unroll
            for (int mt = 0; mt < 2; mt++) {
                const int row = wm * 32 + mt * 16 + (lane >> 2);
                const uint32_t* pp = Ps + row * 68 + kb * 8 + (lane & 3);
                pa[mt][0] = pp[0];
                pa[mt][1] = pp[8 * 68];
                pa[mt][2] = pp[4];
                pa[mt][3] = pp[8 * 68 + 4];
            }
            #pragma unroll
            for (int nd = 0; nd < 2; nd++) {
                const uint32_t* p = Vs + ((wn * 2 + nd) * 8 + kb) * 88 + lane;
                vb[nd][0] = p[0];
                vb[nd][1] = p[36];
            }
            #pragma unroll
            for (int mt = 0; mt < 2; mt++)
                #pragma unroll
                for (int nd = 0; nd < 2; nd++)
                    mma_bf16(oacc[mt][nd], pa[mt], vb[nd]);
        }
    }

    // ---- reduce rowsums: quad shuffles + cross-warp (wn) smem atomics ----
    #pragma unroll
    for (int mt = 0; mt < 2; mt++) {
        float v0 = rs0[mt], v1 = rs1[mt];
        v0 += __shfl_xor_sync(0xffffffffu, v0, 1);
        v0 += __shfl_xor_sync(0xffffffffu, v0, 2);
        v1 += __shfl_xor_sync(0xffffffffu, v1, 1);
        v1 += __shfl_xor_sync(0xffffffffu, v1, 2);
        if ((lane & 3) == 0) {
            const int row = wm * 32 + mt * 16 + (lane >> 2);
            atomicAdd(&rowsum[row], v0);
            atomicAdd(&rowsum[row + 8], v1);
        }
    }
    __syncthreads();

    // ---- normalize + store ----
    float* Oc = g_ctx + (size_t)r * CHUNK_ELEMS + qt * 8192;
    #pragma unroll
    for (int mt = 0; mt < 2; mt++) {
        const int row = wm * 32 + mt * 16 + (lane >> 2);
        const float inv0 = 1.0f / fmaxf(rowsum[row], 2e-15f);
        const float inv1 = 1.0f / fmaxf(rowsum[row + 8], 2e-15f);
        #pragma unroll
        for (int nd = 0; nd < 2; nd++) {
            const int col = wn * 16 + nd * 8 + 2 * (lane & 3);
            float2 o0 = make_float2(oacc[mt][nd][0] * inv0, oacc[mt][nd][1] * inv0);
            float2 o1 = make_float2(oacc[mt][nd][2] * inv1, oacc[mt][nd][3] * inv1);
            *(float2*)&Oc[row * 64 + col]       = o0;
            *(float2*)&Oc[(row + 8) * 64 + col] = o1;
        }
    }
}

// ---------------------------------------------------------------------------
// Residual + LayerNorm (unchanged)
// ---------------------------------------------------------------------------
__global__ void __launch_bounds__(256) resid_ln_kernel(
    const float* __restrict__ resid, const float* __restrict__ gamma,
    const float* __restrict__ beta, float* __restrict__ out)
{
    __shared__ float red[8];
    __shared__ float bc;

    const int row = blockIdx.x;
    const int tid = threadIdx.x;
    const float* pr = g_proj + (size_t)row * 1024;
    const float* rr = resid + (size_t)row * 1024;

    float x[4];
    float sum = 0.0f;
    #pragma unroll
    for (int c = 0; c < 4; c++) {
        x[c] = rr[tid + 256 * c] + pr[tid + 256 * c];
        sum += x[c];
    }
    #pragma unroll
    for (int m = 16; m; m >>= 1) sum += __shfl_xor_sync(0xffffffffu, sum, m);
    if ((tid & 31) == 0) red[tid >> 5] = sum;
    __syncthreads();
    if (tid == 0) {
        float t = 0.0f;
        #pragma unroll
        for (int i = 0; i < 8; i++) t += red[i];
        bc = t;
    }
    __syncthreads();
    const float mean = bc * (1.0f / 1024.0f);

    float vs = 0.0f;
    #pragma unroll
    for (int c = 0; c < 4; c++) { float d = x[c] - mean; vs += d * d; }
    #pragma unroll
    for (int m = 16; m; m >>= 1) vs += __shfl_xor_sync(0xffffffffu, vs, m);
    __syncthreads();
    if ((tid & 31) == 0) red[tid >> 5] = vs;
    __syncthreads();
    if (tid == 0) {
        float t = 0.0f;
        #pragma unroll
        for (int i = 0; i < 8; i++) t += red[i];
        bc = t;
    }
    __syncthreads();
    const float var = bc * (1.0f / 1024.0f);
    const float inv = rsqrtf(var + 1e-5f);

    #pragma unroll
    for (int c = 0; c < 4; c++) {
        int idx = tid + 256 * c;
        out[(size_t)row * 1024 + idx] =
            (x[c] - mean) * inv * gamma[idx] + beta[idx];
    }
}

// ---------------------------------------------------------------------------
// Host launcher
// ---------------------------------------------------------------------------
extern "C" void kernel_launch(void* const* d_in, const int* in_sizes, int n_in,
                              void* d_out, int out_size)
{
    const float* query  = (const float*)d_in[0];
    const float* key    = (const float*)d_in[1];
    const float* value  = (const float*)d_in[2];
    const float* q_mask = (const float*)d_in[3];
    const float* k_mask = (const float*)d_in[4];
    const float* Wq     = (const float*)d_in[5];
    const float* bq     = (const float*)d_in[6];
    const float* Wk     = (const float*)d_in[7];
    const float* bk     = (const float*)d_in[8];
    const float* Wv     = (const float*)d_in[9];
    const float* bv     = (const float*)d_in[10];
    const float* Wo     = (const float*)d_in[11];
    const float* bo     = (const float*)d_in[12];
    const float* gamma  = (const float*)d_in[13];
    const float* beta   = (const float*)d_in[14];
    float* out = (float*)d_out;

    (void)in_sizes; (void)n_in; (void)out_size;

    cudaFuncSetAttribute(attn_bf16_kernel,
                         cudaFuncAttributeMaxDynamicSharedMemorySize,
                         AT_SMEM_BYTES);
    cudaFuncSetAttribute(gemm_bf16,
                         cudaFuncAttributeMaxDynamicSharedMemorySize,
                         GT_SMEM_BYTES);

    float *gq, *gk, *gv, *gctx, *gproj;
    cudaGetSymbolAddress((void**)&gq,    g_q);
    cudaGetSymbolAddress((void**)&gk,    g_k);
    cudaGetSymbolAddress((void**)&gv,    g_v);
    cudaGetSymbolAddress((void**)&gctx,  g_ctx);
    cudaGetSymbolAddress((void**)&gproj, g_proj);

    dim3 ggrid(DIM / 128, M_ROWS / 128);   // (8, 64)

    gemm_bf16<<<ggrid, 256, GT_SMEM_BYTES>>>(query, Wq, bq, gq);
    gemm_bf16<<<ggrid, 256, GT_SMEM_BYTES>>>(key,   Wk, bk, gk);
    gemm_bf16<<<ggrid, 256, GT_SMEM_BYTES>>>(value, Wv, bv, gv);

    attn_bf16_kernel<<<dim3(NCHUNK, 8), 512, AT_SMEM_BYTES>>>(q_mask, k_mask);

    gemm_bf16<<<ggrid, 256, GT_SMEM_BYTES>>>(gctx, Wo, bo, gproj);

    resid_ln_kernel<<<M_ROWS, 256>>>(query, gamma, beta, out);
}

// round 8
// speedup vs baseline: 2.7299x; 1.1556x over previous
#include <cuda_runtime.h>
#include <cuda_bf16.h>
#include <cstdint>
#include <math.h>

// ---------------------------------------------------------------------------
// B=8, L=1024, D=1024, H=16, d=64.  M = 8192 token rows.
// GEMMs + attention: mma.sync bf16 m16n8k16 fed by ldmatrix (swizzled smem).
// ---------------------------------------------------------------------------

#define M_ROWS  8192
#define DIM     1024
#define NCHUNK  128
#define CHUNK_ELEMS 65536

__device__ float g_q[M_ROWS * DIM];
__device__ float g_k[M_ROWS * DIM];
__device__ float g_v[M_ROWS * DIM];
__device__ float g_ctx[M_ROWS * DIM];
__device__ float g_proj[M_ROWS * DIM];

__device__ __forceinline__ uint32_t smem_u32(const void* p) {
    uint32_t a;
    asm("{ .reg .u64 t; cvta.to.shared.u64 t, %1; cvt.u32.u64 %0, t; }"
        : "=r"(a) : "l"(p));
    return a;
}
__device__ __forceinline__ uint32_t packbf(float a, float b) {
    __nv_bfloat162 t = __floats2bfloat162_rn(a, b);
    return *reinterpret_cast<uint32_t*>(&t);
}
__device__ __forceinline__ void mma_bf16(float* c, const uint32_t* a,
                                         const uint32_t* b) {
    asm volatile(
        "mma.sync.aligned.m16n8k16.row.col.f32.bf16.bf16.f32 "
        "{%0,%1,%2,%3}, {%4,%5,%6,%7}, {%8,%9}, {%0,%1,%2,%3};"
        : "+f"(c[0]), "+f"(c[1]), "+f"(c[2]), "+f"(c[3])
        : "r"(a[0]), "r"(a[1]), "r"(a[2]), "r"(a[3]), "r"(b[0]), "r"(b[1]));
}
#define LDM_X4(r0, r1, r2, r3, addr) \
    asm volatile("ldmatrix.sync.aligned.m8n8.x4.shared.b16 {%0,%1,%2,%3}, [%4];" \
        : "=r"(r0), "=r"(r1), "=r"(r2), "=r"(r3) : "r"(addr))
#define LDM_X4T(r0, r1, r2, r3, addr) \
    asm volatile("ldmatrix.sync.aligned.m8n8.x4.trans.shared.b16 {%0,%1,%2,%3}, [%4];" \
        : "=r"(r0), "=r"(r1), "=r"(r2), "=r"(r3) : "r"(addr))

// Swizzled tile: 128 rows x 32 bf16 (2048 words). Two rows share a 128B line.
// word_off(m, k); chunk' = ((m&1)*4 | k>>3) ^ ((m>>1)&7).
// Conflict-free for STS.128 loaders, 32-bit P stores, and all ldmatrix shapes.
__device__ __forceinline__ uint32_t swz(int m, int k) {
    return (uint32_t)(((m >> 1) << 5)
        + (((((m & 1) << 2) | (k >> 3)) ^ ((m >> 1) & 7)) << 2)
        + ((k >> 1) & 3));
}

// ---------------------------------------------------------------------------
// bf16 GEMM via ldmatrix: C = A @ W^T + bias.  CTA 128x128, 256 thr,
// warps 2m x 4n (warp tile 64x32), K chunks of 32, double buffer, 2 CTAs/SM.
// Smem words: [bufA 2048 | bufB 2048] x2 = 32 KB.  Batched over blockIdx.z.
// ---------------------------------------------------------------------------
struct GemmPtrs {
    const float* A[3]; const float* W[3]; const float* bias[3]; float* C[3];
};
#define GEMM_SMEM_BYTES 32768
#define GEMM_BUF_WORDS  4096

__global__ void __launch_bounds__(256, 2) gemm_bf16_lm(GemmPtrs gp)
{
    extern __shared__ __align__(16) uint32_t smg[];
    const uint32_t sb = smem_u32(smg);
    const int z = blockIdx.z;
    const float* A    = gp.A[z];
    const float* W    = gp.W[z];
    const float* bias = gp.bias[z];
    float* C          = gp.C[z];

    const int tid  = threadIdx.x;
    const int lane = tid & 31;
    const int wid  = tid >> 5;
    const int wm   = wid & 1;
    const int wn   = wid >> 1;
    const int row0 = blockIdx.y * 128;
    const int col0 = blockIdx.x * 128;

    // loader: thread -> row m, k-half h (16 fp32 each)
    const int m  = tid & 127;
    const int h  = tid >> 7;
    const int k0 = h * 16;
    const float* Ap = A + (size_t)(row0 + m) * DIM + k0;
    const float* Wp = W + (size_t)(col0 + m) * DIM + k0;
    const uint32_t wA0 = swz(m, k0), wA1 = swz(m, k0 + 8);
    const uint32_t wB0 = 2048 + swz(m, k0), wB1 = 2048 + swz(m, k0 + 8);

    // ldmatrix lane addresses (byte, shared space)
    const int g = lane >> 3, li = lane & 7;
    const int aml = wm * 64 + (g & 1) * 8 + li;
    const int bnl = wn * 32 + ((g >> 1) & 1) * 8 + li;
    uint32_t aAddr[2], bAddr[2];
    #pragma unroll
    for (int ks = 0; ks < 2; ks++) {
        aAddr[ks] = sb + swz(aml, ks * 16 + (g >> 1) * 8) * 4;
        bAddr[ks] = sb + (2048 + swz(bnl, ks * 16 + (g & 1) * 8)) * 4;
    }

    float acc[4][4][4];
    #pragma unroll
    for (int mt = 0; mt < 4; mt++)
        #pragma unroll
        for (int nt = 0; nt < 4; nt++)
            #pragma unroll
            for (int f = 0; f < 4; f++) acc[mt][nt][f] = 0.0f;

    // prologue: chunk 0
    {
        float4 v0 = *(const float4*)(Ap);
        float4 v1 = *(const float4*)(Ap + 4);
        float4 v2 = *(const float4*)(Ap + 8);
        float4 v3 = *(const float4*)(Ap + 12);
        *(uint4*)(smg + wA0) = make_uint4(packbf(v0.x, v0.y), packbf(v0.z, v0.w),
                                          packbf(v1.x, v1.y), packbf(v1.z, v1.w));
        *(uint4*)(smg + wA1) = make_uint4(packbf(v2.x, v2.y), packbf(v2.z, v2.w),
                                          packbf(v3.x, v3.y), packbf(v3.z, v3.w));
        v0 = *(const float4*)(Wp);
        v1 = *(const float4*)(Wp + 4);
        v2 = *(const float4*)(Wp + 8);
        v3 = *(const float4*)(Wp + 12);
        *(uint4*)(smg + wB0) = make_uint4(packbf(v0.x, v0.y), packbf(v0.z, v0.w),
                                          packbf(v1.x, v1.y), packbf(v1.z, v1.w));
        *(uint4*)(smg + wB1) = make_uint4(packbf(v2.x, v2.y), packbf(v2.z, v2.w),
                                          packbf(v3.x, v3.y), packbf(v3.z, v3.w));
    }
    __syncthreads();

    for (int c = 0; c < 32; ++c) {
        const int cur = c & 1, nxt = cur ^ 1;
        uint4 pa0, pa1, pb0, pb1;
        if (c < 31) {
            const float* Ap2 = Ap + (c + 1) * 32;
            const float* Wp2 = Wp + (c + 1) * 32;
            float4 v0 = *(const float4*)(Ap2);
            float4 v1 = *(const float4*)(Ap2 + 4);
            float4 v2 = *(const float4*)(Ap2 + 8);
            float4 v3 = *(const float4*)(Ap2 + 12);
            pa0 = make_uint4(packbf(v0.x, v0.y), packbf(v0.z, v0.w),
                             packbf(v1.x, v1.y), packbf(v1.z, v1.w));
            pa1 = make_uint4(packbf(v2.x, v2.y), packbf(v2.z, v2.w),
                             packbf(v3.x, v3.y), packbf(v3.z, v3.w));
            v0 = *(const float4*)(Wp2);
            v1 = *(const float4*)(Wp2 + 4);
            v2 = *(const float4*)(Wp2 + 8);
            v3 = *(const float4*)(Wp2 + 12);
            pb0 = make_uint4(packbf(v0.x, v0.y), packbf(v0.z, v0.w),
                             packbf(v1.x, v1.y), packbf(v1.z, v1.w));
            pb1 = make_uint4(packbf(v2.x, v2.y), packbf(v2.z, v2.w),
                             packbf(v3.x, v3.y), packbf(v3.z, v3.w));
        }

        const uint32_t off = cur * (GEMM_BUF_WORDS * 4);   // byte offset
        #pragma unroll
        for (int ks = 0; ks < 2; ks++) {
            uint32_t af[4][4], bfr[4][2];
            #pragma unroll
            for (int mt = 0; mt < 4; mt++)
                LDM_X4(af[mt][0], af[mt][1], af[mt][2], af[mt][3],
                       aAddr[ks] + off + mt * 1024);
            #pragma unroll
            for (int pr = 0; pr < 2; pr++) {
                uint32_t r0, r1, r2, r3;
                LDM_X4(r0, r1, r2, r3, bAddr[ks] + off + pr * 1024);
                bfr[pr * 2][0] = r0; bfr[pr * 2][1] = r1;
                bfr[pr * 2 + 1][0] = r2; bfr[pr * 2 + 1][1] = r3;
            }
            #pragma unroll
            for (int mt = 0; mt < 4; mt++)
                #pragma unroll
                for (int nt = 0; nt < 4; nt++)
                    mma_bf16(acc[mt][nt], af[mt], bfr[nt]);
        }

        if (c < 31) {
            uint32_t* base = smg + nxt * GEMM_BUF_WORDS;
            *(uint4*)(base + wA0) = pa0;
            *(uint4*)(base + wA1) = pa1;
            *(uint4*)(base + wB0) = pb0;
            *(uint4*)(base + wB1) = pb1;
        }
        __syncthreads();
    }

    const int qr = lane >> 2;
    const int qc = (lane & 3) * 2;
    #pragma unroll
    for (int nt = 0; nt < 4; nt++) {
        const int cc = col0 + wn * 32 + nt * 8 + qc;
        const float b0 = bias[cc], b1 = bias[cc + 1];
        #pragma unroll
        for (int mt = 0; mt < 4; mt++) {
            const int rr = row0 + wm * 64 + mt * 16 + qr;
            float2 o0 = make_float2(acc[mt][nt][0] + b0, acc[mt][nt][1] + b1);
            float2 o1 = make_float2(acc[mt][nt][2] + b0, acc[mt][nt][3] + b1);
            *(float2*)(C + (size_t)rr * DIM + cc)       = o0;
            *(float2*)(C + (size_t)(rr + 8) * DIM + cc) = o1;
        }
    }
}

// ---------------------------------------------------------------------------
// Attention, bf16 mma + ldmatrix.  512 thr (16 warps, 4m x 4n).
// Smem words: Qs[2x2048] | Ks[2x2048] | Vs[2x2048] | Ps[4x2048] | masks/rowsum
// ---------------------------------------------------------------------------
#define AT_KS_OFF 4096
#define AT_VS_OFF 8192
#define AT_PS_OFF 12288
#define AT_QM 20480
#define AT_KM 20608
#define AT_RS 20736
#define AT_WORDS 20864
#define AT_SMEM_BYTES (AT_WORDS * 4)   // 83456

__global__ void __launch_bounds__(512) attn_bf16_lm(
    const float* __restrict__ qmask, const float* __restrict__ kmask)
{
    extern __shared__ __align__(16) uint32_t smw[];
    const uint32_t sbb = smem_u32(smw);
    float* qmr    = (float*)(smw + AT_QM);
    float* kmr    = (float*)(smw + AT_KM);
    float* rowsum = (float*)(smw + AT_RS);

    const int tid  = threadIdx.x;
    const int lane = tid & 31;
    const int wid  = tid >> 5;
    const int wm   = wid & 3;
    const int wn   = wid >> 2;
    const int r    = blockIdx.x;
    const int qt   = blockIdx.y;

    const float* Qc = g_q + (size_t)r * CHUNK_ELEMS + qt * 8192;
    const float* Kc = g_k + (size_t)r * CHUNK_ELEMS;
    const float* Vc = g_v + (size_t)r * CHUNK_ELEMS;

    const int lm = tid & 127;          // loader row
    const int lq = tid >> 7;           // 0..3
    const int lk = lq * 16;            // k offset (of 64)
    const uint32_t lw0 = (lk >> 5) * 2048 + swz(lm, lk & 31);
    const uint32_t lw1 = (lk >> 5) * 2048 + swz(lm, (lk & 31) + 8);

    // ---- Q load (once) ----
    {
        const float* src = Qc + lm * 64 + lk;
        float4 v0 = *(const float4*)(src);
        float4 v1 = *(const float4*)(src + 4);
        float4 v2 = *(const float4*)(src + 8);
        float4 v3 = *(const float4*)(src + 12);
        *(uint4*)(smw + lw0) = make_uint4(packbf(v0.x, v0.y), packbf(v0.z, v0.w),
                                          packbf(v1.x, v1.y), packbf(v1.z, v1.w));
        *(uint4*)(smw + lw1) = make_uint4(packbf(v2.x, v2.y), packbf(v2.z, v2.w),
                                          packbf(v3.x, v3.y), packbf(v3.z, v3.w));
    }
    if (tid < 128) {
        qmr[tid] = qmask[(r & 7) * 1024 + qt * 128 + tid];
        rowsum[tid] = 0.0f;
    }

    const int g = lane >> 3, li = lane & 7;

    float oacc[2][2][4];
    #pragma unroll
    for (int mt = 0; mt < 2; mt++)
        #pragma unroll
        for (int nd = 0; nd < 2; nd++)
            #pragma unroll
            for (int f = 0; f < 4; f++) oacc[mt][nd][f] = 0.0f;
    float rs0[2] = {0, 0}, rs1[2] = {0, 0};

    for (int kt = 0; kt < 8; kt++) {
        __syncthreads();
        // ---- K,V loaders ----
        {
            const float* src = Kc + kt * 8192 + lm * 64 + lk;
            float4 v0 = *(const float4*)(src);
            float4 v1 = *(const float4*)(src + 4);
            float4 v2 = *(const float4*)(src + 8);
            float4 v3 = *(const float4*)(src + 12);
            *(uint4*)(smw + AT_KS_OFF + lw0) =
                make_uint4(packbf(v0.x, v0.y), packbf(v0.z, v0.w),
                           packbf(v1.x, v1.y), packbf(v1.z, v1.w));
            *(uint4*)(smw + AT_KS_OFF + lw1) =
                make_uint4(packbf(v2.x, v2.y), packbf(v2.z, v2.w),
                           packbf(v3.x, v3.y), packbf(v3.z, v3.w));
            src = Vc + kt * 8192 + lm * 64 + lk;
            v0 = *(const float4*)(src);
            v1 = *(const float4*)(src + 4);
            v2 = *(const float4*)(src + 8);
            v3 = *(const float4*)(src + 12);
            *(uint4*)(smw + AT_VS_OFF + lw0) =
                make_uint4(packbf(v0.x, v0.y), packbf(v0.z, v0.w),
                           packbf(v1.x, v1.y), packbf(v1.z, v1.w));
            *(uint4*)(smw + AT_VS_OFF + lw1) =
                make_uint4(packbf(v2.x, v2.y), packbf(v2.z, v2.w),
                           packbf(v3.x, v3.y), packbf(v3.z, v3.w));
        }
        if (tid < 128)
            kmr[tid] = kmask[(r & 7) * 1024 + kt * 128 + tid];
        __syncthreads();

        // ---- S = Q K^T ----
        float sacc[2][4][4];
        #pragma unroll
        for (int mt = 0; mt < 2; mt++)
            #pragma unroll
            for (int nt = 0; nt < 4; nt++)
                #pragma unroll
                for (int f = 0; f < 4; f++) sacc[mt][nt][f] = 0.0f;

        #pragma unroll
        for (int ks = 0; ks < 4; ks++) {
            uint32_t af[2][4], bfr[4][2];
            #pragma unroll
            for (int mt = 0; mt < 2; mt++) {
                const int ml = wm * 32 + mt * 16 + (g & 1) * 8 + li;
                const int kl = ks * 16 + (g >> 1) * 8;
                const uint32_t ad = sbb + ((kl >> 5) * 2048 + swz(ml, kl & 31)) * 4;
                LDM_X4(af[mt][0], af[mt][1], af[mt][2], af[mt][3], ad);
            }
            #pragma unroll
            for (int pr = 0; pr < 2; pr++) {
                const int nl = wn * 32 + pr * 16 + ((g >> 1) & 1) * 8 + li;
                const int kl = ks * 16 + (g & 1) * 8;
                const uint32_t ad = sbb + (AT_KS_OFF + (kl >> 5) * 2048
                                           + swz(nl, kl & 31)) * 4;
                uint32_t r0, r1, r2, r3;
                LDM_X4(r0, r1, r2, r3, ad);
                bfr[pr * 2][0] = r0; bfr[pr * 2][1] = r1;
                bfr[pr * 2 + 1][0] = r2; bfr[pr * 2 + 1][1] = r3;
            }
            #pragma unroll
            for (int mt = 0; mt < 2; mt++)
                #pragma unroll
                for (int nt = 0; nt < 4; nt++)
                    mma_bf16(sacc[mt][nt], af[mt], bfr[nt]);
        }

        // ---- P = mask ? exp(S/8) : 0 ; store packed to swizzled Ps ----
        #pragma unroll
        for (int mt = 0; mt < 2; mt++) {
            const int row = wm * 32 + mt * 16 + (lane >> 2);
            const float qm0 = qmr[row], qm1 = qmr[row + 8];
            #pragma unroll
            for (int nt = 0; nt < 4; nt++) {
                const int colp = wn * 16 + nt * 4 + (lane & 3);   // key pair
                const float km0 = kmr[2 * colp], km1 = kmr[2 * colp + 1];
                float p0 = (qm0 * km0 == 0.0f) ? 0.0f : __expf(sacc[mt][nt][0] * 0.125f);
                float p1 = (qm0 * km1 == 0.0f) ? 0.0f : __expf(sacc[mt][nt][1] * 0.125f);
                float p2 = (qm1 * km0 == 0.0f) ? 0.0f : __expf(sacc[mt][nt][2] * 0.125f);
                float p3 = (qm1 * km1 == 0.0f) ? 0.0f : __expf(sacc[mt][nt][3] * 0.125f);
                uint32_t w0 = packbf(p0, p1);
                uint32_t w1 = packbf(p2, p3);
                float2 f0 = __bfloat1622float2(*(__nv_bfloat162*)&w0);
                float2 f1 = __bfloat1622float2(*(__nv_bfloat162*)&w1);
                rs0[mt] += f0.x + f0.y;
                rs1[mt] += f1.x + f1.y;
                const int tile = colp >> 4;
                const int kk = (colp & 15) * 2;
                smw[AT_PS_OFF + tile * 2048 + swz(row, kk)]     = w0;
                smw[AT_PS_OFF + tile * 2048 + swz(row + 8, kk)] = w1;
            }
        }
        __syncthreads();

        // ---- O += P V ----
        #pragma unroll
        for (int kb = 0; kb < 8; kb++) {
            uint32_t pa[2][4], vb[2][2];
            #pragma unroll
            for (int mt = 0; mt < 2; mt++) {
                const int ml = wm * 32 + mt * 16 + (g & 1) * 8 + li;
                const int kl = kb * 16 + (g >> 1) * 8;
                const uint32_t ad = sbb + (AT_PS_OFF + (kl >> 5) * 2048
                                           + swz(ml, kl & 31)) * 4;
                LDM_X4(pa[mt][0], pa[mt][1], pa[mt][2], pa[mt][3], ad);
            }
            {
                const int rowl = kb * 16 + (g & 1) * 8 + li;       // key row
                const int dl   = wn * 16 + (g >> 1) * 8;           // d offset
                const uint32_t ad = sbb + (AT_VS_OFF + (dl >> 5) * 2048
                                           + swz(rowl, dl & 31)) * 4;
                uint32_t r0, r1, r2, r3;
                LDM_X4T(r0, r1, r2, r3, ad);
                vb[0][0] = r0; vb[0][1] = r1;
                vb[1][0] = r2; vb[1][1] = r3;
            }
            #pragma unroll
            for (int mt = 0; mt < 2; mt++)
                #pragma unroll
                for (int nd = 0; nd < 2; nd++)
                    mma_bf16(oacc[mt][nd], pa[mt], vb[nd]);
        }
    }

    // ---- rowsum reduction ----
    #pragma unroll
    for (int mt = 0; mt < 2; mt++) {
        float v0 = rs0[mt], v1 = rs1[mt];
        v0 += __shfl_xor_sync(0xffffffffu, v0, 1);
        v0 += __shfl_xor_sync(0xffffffffu, v0, 2);
        v1 += __shfl_xor_sync(0xffffffffu, v1, 1);
        v1 += __shfl_xor_sync(0xffffffffu, v1, 2);
        if ((lane & 3) == 0) {
            const int row = wm * 32 + mt * 16 + (lane >> 2);
            atomicAdd(&rowsum[row], v0);
            atomicAdd(&rowsum[row + 8], v1);
        }
    }
    __syncthreads();

    // ---- normalize + store ----
    float* Oc = g_ctx + (size_t)r * CHUNK_ELEMS + qt * 8192;
    #pragma unroll
    for (int mt = 0; mt < 2; mt++) {
        const int row = wm * 32 + mt * 16 + (lane >> 2);
        const float inv0 = 1.0f / fmaxf(rowsum[row], 2e-15f);
        const float inv1 = 1.0f / fmaxf(rowsum[row + 8], 2e-15f);
        #pragma unroll
        for (int nd = 0; nd < 2; nd++) {
            const int col = wn * 16 + nd * 8 + 2 * (lane & 3);
            float2 o0 = make_float2(oacc[mt][nd][0] * inv0, oacc[mt][nd][1] * inv0);
            float2 o1 = make_float2(oacc[mt][nd][2] * inv1, oacc[mt][nd][3] * inv1);
            *(float2*)&Oc[row * 64 + col]       = o0;
            *(float2*)&Oc[(row + 8) * 64 + col] = o1;
        }
    }
}

// ---------------------------------------------------------------------------
// Residual + LayerNorm (unchanged)
// ---------------------------------------------------------------------------
__global__ void __launch_bounds__(256) resid_ln_kernel(
    const float* __restrict__ resid, const float* __restrict__ gamma,
    const float* __restrict__ beta, float* __restrict__ out)
{
    __shared__ float red[8];
    __shared__ float bc;

    const int row = blockIdx.x;
    const int tid = threadIdx.x;
    const float* pr = g_proj + (size_t)row * 1024;
    const float* rr = resid + (size_t)row * 1024;

    float x[4];
    float sum = 0.0f;
    #pragma unroll
    for (int c = 0; c < 4; c++) {
        x[c] = rr[tid + 256 * c] + pr[tid + 256 * c];
        sum += x[c];
    }
    #pragma unroll
    for (int m = 16; m; m >>= 1) sum += __shfl_xor_sync(0xffffffffu, sum, m);
    if ((tid & 31) == 0) red[tid >> 5] = sum;
    __syncthreads();
    if (tid == 0) {
        float t = 0.0f;
        #pragma unroll
        for (int i = 0; i < 8; i++) t += red[i];
        bc = t;
    }
    __syncthreads();
    const float mean = bc * (1.0f / 1024.0f);

    float vs = 0.0f;
    #pragma unroll
    for (int c = 0; c < 4; c++) { float d = x[c] - mean; vs += d * d; }
    #pragma unroll
    for (int m = 16; m; m >>= 1) vs += __shfl_xor_sync(0xffffffffu, vs, m);
    __syncthreads();
    if ((tid & 31) == 0) red[tid >> 5] = vs;
    __syncthreads();
    if (tid == 0) {
        float t = 0.0f;
        #pragma unroll
        for (int i = 0; i < 8; i++) t += red[i];
        bc = t;
    }
    __syncthreads();
    const float var = bc * (1.0f / 1024.0f);
    const float inv = rsqrtf(var + 1e-5f);

    #pragma unroll
    for (int c = 0; c < 4; c++) {
        int idx = tid + 256 * c;
        out[(size_t)row * 1024 + idx] =
            (x[c] - mean) * inv * gamma[idx] + beta[idx];
    }
}

// ---------------------------------------------------------------------------
// Host launcher
// ---------------------------------------------------------------------------
extern "C" void kernel_launch(void* const* d_in, const int* in_sizes, int n_in,
                              void* d_out, int out_size)
{
    const float* query  = (const float*)d_in[0];
    const float* key    = (const float*)d_in[1];
    const float* value  = (const float*)d_in[2];
    const float* q_mask = (const float*)d_in[3];
    const float* k_mask = (const float*)d_in[4];
    const float* Wq     = (const float*)d_in[5];
    const float* bq     = (const float*)d_in[6];
    const float* Wk     = (const float*)d_in[7];
    const float* bk     = (const float*)d_in[8];
    const float* Wv     = (const float*)d_in[9];
    const float* bv     = (const float*)d_in[10];
    const float* Wo     = (const float*)d_in[11];
    const float* bo     = (const float*)d_in[12];
    const float* gamma  = (const float*)d_in[13];
    const float* beta   = (const float*)d_in[14];
    float* out = (float*)d_out;

    (void)in_sizes; (void)n_in; (void)out_size;

    cudaFuncSetAttribute(attn_bf16_lm,
                         cudaFuncAttributeMaxDynamicSharedMemorySize,
                         AT_SMEM_BYTES);
    cudaFuncSetAttribute(gemm_bf16_lm,
                         cudaFuncAttributeMaxDynamicSharedMemorySize,
                         GEMM_SMEM_BYTES);

    float *gq, *gk, *gv, *gctx, *gproj;
    cudaGetSymbolAddress((void**)&gq,    g_q);
    cudaGetSymbolAddress((void**)&gk,    g_k);
    cudaGetSymbolAddress((void**)&gv,    g_v);
    cudaGetSymbolAddress((void**)&gctx,  g_ctx);
    cudaGetSymbolAddress((void**)&gproj, g_proj);

    GemmPtrs g3;
    g3.A[0] = query; g3.W[0] = Wq; g3.bias[0] = bq; g3.C[0] = gq;
    g3.A[1] = key;   g3.W[1] = Wk; g3.bias[1] = bk; g3.C[1] = gk;
    g3.A[2] = value; g3.W[2] = Wv; g3.bias[2] = bv; g3.C[2] = gv;
    gemm_bf16_lm<<<dim3(8, 64, 3), 256, GEMM_SMEM_BYTES>>>(g3);

    attn_bf16_lm<<<dim3(NCHUNK, 8), 512, AT_SMEM_BYTES>>>(q_mask, k_mask);

    GemmPtrs g1;
    g1.A[0] = gctx; g1.W[0] = Wo; g1.bias[0] = bo; g1.C[0] = gproj;
    g1.A[1] = gctx; g1.W[1] = Wo; g1.bias[1] = bo; g1.C[1] = gproj;
    g1.A[2] = gctx; g1.W[2] = Wo; g1.bias[2] = bo; g1.C[2] = gproj;
    gemm_bf16_lm<<<dim3(8, 64, 1), 256, GEMM_SMEM_BYTES>>>(g1);

    resid_ln_kernel<<<M_ROWS, 256>>>(query, gamma, beta, out);
}

// round 9
// speedup vs baseline: 4.2545x; 1.5585x over previous
#include <cuda_runtime.h>
#include <cuda_bf16.h>
#include <cstdint>
#include <math.h>

// ---------------------------------------------------------------------------
// B=8, L=1024, D=1024, H=16, d=64.  M = 8192 token rows.
// bf16 mma.sync + ldmatrix + cp.async; operands pre-converted to bf16 once.
// ---------------------------------------------------------------------------

#define M_ROWS  8192
#define DIM     1024
#define NCHUNK  128
#define CHUNK_ELEMS 65536

typedef __nv_bfloat16 bf16;

// bf16 scratch
__device__ bf16 g_inb[3][M_ROWS * DIM];    // query/key/value inputs, bf16
__device__ bf16 g_wb[4][DIM * DIM];        // Wq,Wk,Wv,Wo bf16
__device__ bf16 g_pq[M_ROWS * DIM];        // projection outputs (bf16)
__device__ bf16 g_pk[M_ROWS * DIM];
__device__ bf16 g_pv[M_ROWS * DIM];
__device__ bf16 g_ctxb[M_ROWS * DIM];      // attention output (bf16)
__device__ float g_proj[M_ROWS * DIM];     // final projection (fp32, for LN)

__device__ __forceinline__ uint32_t smem_u32(const void* p) {
    uint32_t a;
    asm("{ .reg .u64 t; cvta.to.shared.u64 t, %1; cvt.u32.u64 %0, t; }"
        : "=r"(a) : "l"(p));
    return a;
}
__device__ __forceinline__ uint32_t packbf(float a, float b) {
    __nv_bfloat162 t = __floats2bfloat162_rn(a, b);
    return *reinterpret_cast<uint32_t*>(&t);
}
__device__ __forceinline__ void mma_bf16(float* c, const uint32_t* a,
                                         const uint32_t* b) {
    asm volatile(
        "mma.sync.aligned.m16n8k16.row.col.f32.bf16.bf16.f32 "
        "{%0,%1,%2,%3}, {%4,%5,%6,%7}, {%8,%9}, {%0,%1,%2,%3};"
        : "+f"(c[0]), "+f"(c[1]), "+f"(c[2]), "+f"(c[3])
        : "r"(a[0]), "r"(a[1]), "r"(a[2]), "r"(a[3]), "r"(b[0]), "r"(b[1]));
}
#define LDM_X4(r0, r1, r2, r3, addr) \
    asm volatile("ldmatrix.sync.aligned.m8n8.x4.shared.b16 {%0,%1,%2,%3}, [%4];" \
        : "=r"(r0), "=r"(r1), "=r"(r2), "=r"(r3) : "r"(addr))
#define LDM_X4T(r0, r1, r2, r3, addr) \
    asm volatile("ldmatrix.sync.aligned.m8n8.x4.trans.shared.b16 {%0,%1,%2,%3}, [%4];" \
        : "=r"(r0), "=r"(r1), "=r"(r2), "=r"(r3) : "r"(addr))
#define CP16(dst, src) \
    asm volatile("cp.async.cg.shared.global [%0], [%1], 16;" \
        :: "r"(dst), "l"(src) : "memory")
#define CP_COMMIT() asm volatile("cp.async.commit_group;" ::: "memory")
#define CP_WAIT(n)  asm volatile("cp.async.wait_group %0;" :: "n"(n) : "memory")

// Swizzled tile: 128 rows x 32 bf16 (2048 words). word_off(m,k);
// 16B segment = one k-octet; conflict-free for cp.async, stores, ldmatrix.
__device__ __forceinline__ uint32_t swz(int m, int k) {
    return (uint32_t)(((m >> 1) << 5)
        + (((((m & 1) << 2) | (k >> 3)) ^ ((m >> 1) & 7)) << 2)
        + ((k >> 1) & 3));
}

// ---------------------------------------------------------------------------
// fp32 -> bf16 conversion (inputs + weights), one launch, z-batched
// ---------------------------------------------------------------------------
struct CvtPtrs { const float* s[7]; bf16* d[7]; int n[7]; };

__global__ void __launch_bounds__(256) cvt_kernel(CvtPtrs cp)
{
    const int z = blockIdx.y;
    const int n = cp.n[z];
    const int idx = (blockIdx.x * 256 + threadIdx.x) * 4;
    if (idx >= n) return;
    float4 v = *(const float4*)(cp.s[z] + idx);
    uint32_t w0 = packbf(v.x, v.y), w1 = packbf(v.z, v.w);
    *(uint32_t*)(cp.d[z] + idx)     = w0;
    *(uint32_t*)(cp.d[z] + idx + 2) = w1;
}

// ---------------------------------------------------------------------------
// bf16 GEMM, cp.async pipeline: C = A @ W^T + bias.  CTA 128x128, 256 thr,
// warps 2m x 4n, K chunks of 32, double buffer, 2 CTAs/SM.  z-batched.
// ---------------------------------------------------------------------------
struct GemmPtrs {
    const bf16* A[3]; const bf16* W[3]; const float* bias[3];
    bf16* Cb[3]; float* Cf[3]; int write_f32;
};
#define GEMM_SMEM_BYTES 32768
#define GEMM_BUF_WORDS  4096

__global__ void __launch_bounds__(256, 2) gemm_bf16_cp(GemmPtrs gp)
{
    extern __shared__ __align__(16) uint32_t smg[];
    const uint32_t sb = smem_u32(smg);
    const int z = blockIdx.z;
    const bf16* A     = gp.A[z];
    const bf16* W     = gp.W[z];
    const float* bias = gp.bias[z];

    const int tid  = threadIdx.x;
    const int lane = tid & 31;
    const int wid  = tid >> 5;
    const int wm   = wid & 1;
    const int wn   = wid >> 1;
    const int row0 = blockIdx.y * 128;
    const int col0 = blockIdx.x * 128;

    // loader: thread -> row m, k-half h (two 8-elt octets)
    const int m  = tid & 127;
    const int h  = tid >> 7;
    const int k0 = h * 16;
    const bf16* Ap = A + (size_t)(row0 + m) * DIM + k0;
    const bf16* Wp = W + (size_t)(col0 + m) * DIM + k0;
    const uint32_t dA0 = sb + swz(m, k0) * 4;
    const uint32_t dA1 = sb + swz(m, k0 + 8) * 4;
    const uint32_t dB0 = sb + (2048 + swz(m, k0)) * 4;
    const uint32_t dB1 = sb + (2048 + swz(m, k0 + 8)) * 4;

    // ldmatrix lane addresses
    const int g = lane >> 3, li = lane & 7;
    const int aml = wm * 64 + (g & 1) * 8 + li;
    const int bnl = wn * 32 + ((g >> 1) & 1) * 8 + li;
    uint32_t aAddr[2], bAddr[2];
    #pragma unroll
    for (int ks = 0; ks < 2; ks++) {
        aAddr[ks] = sb + swz(aml, ks * 16 + (g >> 1) * 8) * 4;
        bAddr[ks] = sb + (2048 + swz(bnl, ks * 16 + (g & 1) * 8)) * 4;
    }

    float acc[4][4][4];
    #pragma unroll
    for (int mt = 0; mt < 4; mt++)
        #pragma unroll
        for (int nt = 0; nt < 4; nt++)
            #pragma unroll
            for (int f = 0; f < 4; f++) acc[mt][nt][f] = 0.0f;

    // prologue: chunk 0
    CP16(dA0, Ap);     CP16(dA1, Ap + 8);
    CP16(dB0, Wp);     CP16(dB1, Wp + 8);
    CP_COMMIT();

    for (int c = 0; c < 32; ++c) {
        const uint32_t off = (uint32_t)((c & 1) * (GEMM_BUF_WORDS * 4));
        if (c < 31) {
            const uint32_t so = (uint32_t)(((c + 1) & 1) * (GEMM_BUF_WORDS * 4));
            const bf16* Ap2 = Ap + (c + 1) * 32;
            const bf16* Wp2 = Wp + (c + 1) * 32;
            CP16(dA0 + so, Ap2);     CP16(dA1 + so, Ap2 + 8);
            CP16(dB0 + so, Wp2);     CP16(dB1 + so, Wp2 + 8);
            CP_COMMIT();
            CP_WAIT(1);
        } else {
            CP_WAIT(0);
        }
        __syncthreads();

        #pragma unroll
        for (int ks = 0; ks < 2; ks++) {
            uint32_t af[4][4], bfr[4][2];
            #pragma unroll
            for (int mt = 0; mt < 4; mt++)
                LDM_X4(af[mt][0], af[mt][1], af[mt][2], af[mt][3],
                       aAddr[ks] + off + mt * 1024);
            #pragma unroll
            for (int pr = 0; pr < 2; pr++) {
                uint32_t r0, r1, r2, r3;
                LDM_X4(r0, r1, r2, r3, bAddr[ks] + off + pr * 1024);
                bfr[pr * 2][0] = r0; bfr[pr * 2][1] = r1;
                bfr[pr * 2 + 1][0] = r2; bfr[pr * 2 + 1][1] = r3;
            }
            #pragma unroll
            for (int mt = 0; mt < 4; mt++)
                #pragma unroll
                for (int nt = 0; nt < 4; nt++)
                    mma_bf16(acc[mt][nt], af[mt], bfr[nt]);
        }
        __syncthreads();
    }

    const int qr = lane >> 2;
    const int qc = (lane & 3) * 2;
    if (gp.write_f32) {
        float* C = gp.Cf[z];
        #pragma unroll
        for (int nt = 0; nt < 4; nt++) {
            const int cc = col0 + wn * 32 + nt * 8 + qc;
            const float b0 = bias[cc], b1 = bias[cc + 1];
            #pragma unroll
            for (int mt = 0; mt < 4; mt++) {
                const int rr = row0 + wm * 64 + mt * 16 + qr;
                *(float2*)(C + (size_t)rr * DIM + cc) =
                    make_float2(acc[mt][nt][0] + b0, acc[mt][nt][1] + b1);
                *(float2*)(C + (size_t)(rr + 8) * DIM + cc) =
                    make_float2(acc[mt][nt][2] + b0, acc[mt][nt][3] + b1);
            }
        }
    } else {
        bf16* C = gp.Cb[z];
        #pragma unroll
        for (int nt = 0; nt < 4; nt++) {
            const int cc = col0 + wn * 32 + nt * 8 + qc;
            const float b0 = bias[cc], b1 = bias[cc + 1];
            #pragma unroll
            for (int mt = 0; mt < 4; mt++) {
                const int rr = row0 + wm * 64 + mt * 16 + qr;
                *(uint32_t*)(C + (size_t)rr * DIM + cc) =
                    packbf(acc[mt][nt][0] + b0, acc[mt][nt][1] + b1);
                *(uint32_t*)(C + (size_t)(rr + 8) * DIM + cc) =
                    packbf(acc[mt][nt][2] + b0, acc[mt][nt][3] + b1);
            }
        }
    }
}

// ---------------------------------------------------------------------------
// Attention, bf16 mma + ldmatrix + cp.async.  512 thr (16 warps, 4m x 4n).
// Smem words: Qs[2x2048] | Ks[2x2048] | Vs[2x2048] | Ps[4x2048] | masks/rowsum
// ---------------------------------------------------------------------------
#define AT_KS_OFF 4096
#define AT_VS_OFF 8192
#define AT_PS_OFF 12288
#define AT_QM 20480
#define AT_KM 20608
#define AT_RS 20736
#define AT_WORDS 20864
#define AT_SMEM_BYTES (AT_WORDS * 4)   // 83456

__global__ void __launch_bounds__(512) attn_bf16_cp(
    const float* __restrict__ qmask, const float* __restrict__ kmask)
{
    extern __shared__ __align__(16) uint32_t smw[];
    const uint32_t sbb = smem_u32(smw);
    float* qmr    = (float*)(smw + AT_QM);
    float* kmr    = (float*)(smw + AT_KM);
    float* rowsum = (float*)(smw + AT_RS);

    const int tid  = threadIdx.x;
    const int lane = tid & 31;
    const int wid  = tid >> 5;
    const int wm   = wid & 3;
    const int wn   = wid >> 2;
    const int r    = blockIdx.x;
    const int qt   = blockIdx.y;

    const bf16* Qc = g_pq + (size_t)r * CHUNK_ELEMS + qt * 8192;
    const bf16* Kc = g_pk + (size_t)r * CHUNK_ELEMS;
    const bf16* Vc = g_pv + (size_t)r * CHUNK_ELEMS;

    const int lm = tid & 127;          // loader row
    const int lq = tid >> 7;           // 0..3
    const int lk = lq * 16;            // k offset (of 64)
    const uint32_t lw0 = ((lk >> 5) * 2048 + swz(lm, lk & 31)) * 4;
    const uint32_t lw1 = ((lk >> 5) * 2048 + swz(lm, (lk & 31) + 8)) * 4;

    // ---- Q load (once) ----
    CP16(sbb + lw0, Qc + lm * 64 + lk);
    CP16(sbb + lw1, Qc + lm * 64 + lk + 8);
    CP_COMMIT();
    if (tid < 128) {
        qmr[tid] = qmask[(r & 7) * 1024 + qt * 128 + tid];
        rowsum[tid] = 0.0f;
    }

    const int g = lane >> 3, li = lane & 7;

    float oacc[2][2][4];
    #pragma unroll
    for (int mt = 0; mt < 2; mt++)
        #pragma unroll
        for (int nd = 0; nd < 2; nd++)
            #pragma unroll
            for (int f = 0; f < 4; f++) oacc[mt][nd][f] = 0.0f;
    float rs0[2] = {0, 0}, rs1[2] = {0, 0};

    for (int kt = 0; kt < 8; kt++) {
        __syncthreads();
        // ---- K,V cp.async loaders ----
        {
            const bf16* ks_ = Kc + kt * 8192 + lm * 64 + lk;
            const bf16* vs_ = Vc + kt * 8192 + lm * 64 + lk;
            CP16(sbb + AT_KS_OFF * 4 + lw0, ks_);
            CP16(sbb + AT_KS_OFF * 4 + lw1, ks_ + 8);
            CP16(sbb + AT_VS_OFF * 4 + lw0, vs_);
            CP16(sbb + AT_VS_OFF * 4 + lw1, vs_ + 8);
            CP_COMMIT();
        }
        if (tid < 128)
            kmr[tid] = kmask[(r & 7) * 1024 + kt * 128 + tid];
        CP_WAIT(0);
        __syncthreads();

        // ---- S = Q K^T ----
        float sacc[2][4][4];
        #pragma unroll
        for (int mt = 0; mt < 2; mt++)
            #pragma unroll
            for (int nt = 0; nt < 4; nt++)
                #pragma unroll
                for (int f = 0; f < 4; f++) sacc[mt][nt][f] = 0.0f;

        #pragma unroll
        for (int ks = 0; ks < 4; ks++) {
            uint32_t af[2][4], bfr[4][2];
            #pragma unroll
            for (int mt = 0; mt < 2; mt++) {
                const int ml = wm * 32 + mt * 16 + (g & 1) * 8 + li;
                const int kl = ks * 16 + (g >> 1) * 8;
                const uint32_t ad = sbb + ((kl >> 5) * 2048 + swz(ml, kl & 31)) * 4;
                LDM_X4(af[mt][0], af[mt][1], af[mt][2], af[mt][3], ad);
            }
            #pragma unroll
            for (int pr = 0; pr < 2; pr++) {
                const int nl = wn * 32 + pr * 16 + ((g >> 1) & 1) * 8 + li;
                const int kl = ks * 16 + (g & 1) * 8;
                const uint32_t ad = sbb + (AT_KS_OFF + (kl >> 5) * 2048
                                           + swz(nl, kl & 31)) * 4;
                uint32_t r0, r1, r2, r3;
                LDM_X4(r0, r1, r2, r3, ad);
                bfr[pr * 2][0] = r0; bfr[pr * 2][1] = r1;
                bfr[pr * 2 + 1][0] = r2; bfr[pr * 2 + 1][1] = r3;
            }
            #pragma unroll
            for (int mt = 0; mt < 2; mt++)
                #pragma unroll
                for (int nt = 0; nt < 4; nt++)
                    mma_bf16(sacc[mt][nt], af[mt], bfr[nt]);
        }

        // ---- P = mask ? exp(S/8) : 0 ; store packed to swizzled Ps ----
        #pragma unroll
        for (int mt = 0; mt < 2; mt++) {
            const int row = wm * 32 + mt * 16 + (lane >> 2);
            const float qm0 = qmr[row], qm1 = qmr[row + 8];
            #pragma unroll
            for (int nt = 0; nt < 4; nt++) {
                const int colp = wn * 16 + nt * 4 + (lane & 3);   // key pair
                const float km0 = kmr[2 * colp], km1 = kmr[2 * colp + 1];
                float p0 = (qm0 * km0 == 0.0f) ? 0.0f : __expf(sacc[mt][nt][0] * 0.125f);
                float p1 = (qm0 * km1 == 0.0f) ? 0.0f : __expf(sacc[mt][nt][1] * 0.125f);
                float p2 = (qm1 * km0 == 0.0f) ? 0.0f : __expf(sacc[mt][nt][2] * 0.125f);
                float p3 = (qm1 * km1 == 0.0f) ? 0.0f : __expf(sacc[mt][nt][3] * 0.125f);
                uint32_t w0 = packbf(p0, p1);
                uint32_t w1 = packbf(p2, p3);
                float2 f0 = __bfloat1622float2(*(__nv_bfloat162*)&w0);
                float2 f1 = __bfloat1622float2(*(__nv_bfloat162*)&w1);
                rs0[mt] += f0.x + f0.y;
                rs1[mt] += f1.x + f1.y;
                const int tile = colp >> 4;
                const int kk = (colp & 15) * 2;
                smw[AT_PS_OFF + tile * 2048 + swz(row, kk)]     = w0;
                smw[AT_PS_OFF + tile * 2048 + swz(row + 8, kk)] = w1;
            }
        }
        __syncthreads();

        // ---- O += P V ----
        #pragma unroll
        for (int kb = 0; kb < 8; kb++) {
            uint32_t pa[2][4], vb[2][2];
            #pragma unroll
            for (int mt = 0; mt < 2; mt++) {
                const int ml = wm * 32 + mt * 16 + (g & 1) * 8 + li;
                const int kl = kb * 16 + (g >> 1) * 8;
                const uint32_t ad = sbb + (AT_PS_OFF + (kl >> 5) * 2048
                                           + swz(ml, kl & 31)) * 4;
                LDM_X4(pa[mt][0], pa[mt][1], pa[mt][2], pa[mt][3], ad);
            }
            {
                const int rowl = kb * 16 + (g & 1) * 8 + li;       // key row
                const int dl   = wn * 16 + (g >> 1) * 8;           // d offset
                const uint32_t ad = sbb + (AT_VS_OFF + (dl >> 5) * 2048
                                           + swz(rowl, dl & 31)) * 4;
                uint32_t r0, r1, r2, r3;
                LDM_X4T(r0, r1, r2, r3, ad);
                vb[0][0] = r0; vb[0][1] = r1;
                vb[1][0] = r2; vb[1][1] = r3;
            }
            #pragma unroll
            for (int mt = 0; mt < 2; mt++)
                #pragma unroll
                for (int nd = 0; nd < 2; nd++)
                    mma_bf16(oacc[mt][nd], pa[mt], vb[nd]);
        }
    }

    // ---- rowsum reduction ----
    #pragma unroll
    for (int mt = 0; mt < 2; mt++) {
        float v0 = rs0[mt], v1 = rs1[mt];
        v0 += __shfl_xor_sync(0xffffffffu, v0, 1);
        v0 += __shfl_xor_sync(0xffffffffu, v0, 2);
        v1 += __shfl_xor_sync(0xffffffffu, v1, 1);
        v1 += __shfl_xor_sync(0xffffffffu, v1, 2);
        if ((lane & 3) == 0) {
            const int row = wm * 32 + mt * 16 + (lane >> 2);
            atomicAdd(&rowsum[row], v0);
            atomicAdd(&rowsum[row + 8], v1);
        }
    }
    __syncthreads();

    // ---- normalize + store bf16 ctx ----
    bf16* Oc = g_ctxb + (size_t)r * CHUNK_ELEMS + qt * 8192;
    #pragma unroll
    for (int mt = 0; mt < 2; mt++) {
        const int row = wm * 32 + mt * 16 + (lane >> 2);
        const float inv0 = 1.0f / fmaxf(rowsum[row], 2e-15f);
        const float inv1 = 1.0f / fmaxf(rowsum[row + 8], 2e-15f);
        #pragma unroll
        for (int nd = 0; nd < 2; nd++) {
            const int col = wn * 16 + nd * 8 + 2 * (lane & 3);
            *(uint32_t*)(Oc + row * 64 + col) =
                packbf(oacc[mt][nd][0] * inv0, oacc[mt][nd][1] * inv0);
            *(uint32_t*)(Oc + (row + 8) * 64 + col) =
                packbf(oacc[mt][nd][2] * inv1, oacc[mt][nd][3] * inv1);
        }
    }
}

// ---------------------------------------------------------------------------
// Residual + LayerNorm (unchanged)
// ---------------------------------------------------------------------------
__global__ void __launch_bounds__(256) resid_ln_kernel(
    const float* __restrict__ resid, const float* __restrict__ gamma,
    const float* __restrict__ beta, float* __restrict__ out)
{
    __shared__ float red[8];
    __shared__ float bc;

    const int row = blockIdx.x;
    const int tid = threadIdx.x;
    const float* pr = g_proj + (size_t)row * 1024;
    const float* rr = resid + (size_t)row * 1024;

    float x[4];
    float sum = 0.0f;
    #pragma unroll
    for (int c = 0; c < 4; c++) {
        x[c] = rr[tid + 256 * c] + pr[tid + 256 * c];
        sum += x[c];
    }
    #pragma unroll
    for (int m = 16; m; m >>= 1) sum += __shfl_xor_sync(0xffffffffu, sum, m);
    if ((tid & 31) == 0) red[tid >> 5] = sum;
    __syncthreads();
    if (tid == 0) {
        float t = 0.0f;
        #pragma unroll
        for (int i = 0; i < 8; i++) t += red[i];
        bc = t;
    }
    __syncthreads();
    const float mean = bc * (1.0f / 1024.0f);

    float vs = 0.0f;
    #pragma unroll
    for (int c = 0; c < 4; c++) { float d = x[c] - mean; vs += d * d; }
    #pragma unroll
    for (int m = 16; m; m >>= 1) vs += __shfl_xor_sync(0xffffffffu, vs, m);
    __syncthreads();
    if ((tid & 31) == 0) red[tid >> 5] = vs;
    __syncthreads();
    if (tid == 0) {
        float t = 0.0f;
        #pragma unroll
        for (int i = 0; i < 8; i++) t += red[i];
        bc = t;
    }
    __syncthreads();
    const float var = bc * (1.0f / 1024.0f);
    const float inv = rsqrtf(var + 1e-5f);

    #pragma unroll
    for (int c = 0; c < 4; c++) {
        int idx = tid + 256 * c;
        out[(size_t)row * 1024 + idx] =
            (x[c] - mean) * inv * gamma[idx] + beta[idx];
    }
}

// ---------------------------------------------------------------------------
// Host launcher
// ---------------------------------------------------------------------------
extern "C" void kernel_launch(void* const* d_in, const int* in_sizes, int n_in,
                              void* d_out, int out_size)
{
    const float* query  = (const float*)d_in[0];
    const float* key    = (const float*)d_in[1];
    const float* value  = (const float*)d_in[2];
    const float* q_mask = (const float*)d_in[3];
    const float* k_mask = (const float*)d_in[4];
    const float* Wq     = (const float*)d_in[5];
    const float* bq     = (const float*)d_in[6];
    const float* Wk     = (const float*)d_in[7];
    const float* bk     = (const float*)d_in[8];
    const float* Wv     = (const float*)d_in[9];
    const float* bv     = (const float*)d_in[10];
    const float* Wo     = (const float*)d_in[11];
    const float* bo     = (const float*)d_in[12];
    const float* gamma  = (const float*)d_in[13];
    const float* beta   = (const float*)d_in[14];
    float* out = (float*)d_out;

    (void)in_sizes; (void)n_in; (void)out_size;

    cudaFuncSetAttribute(attn_bf16_cp,
                         cudaFuncAttributeMaxDynamicSharedMemorySize,
                         AT_SMEM_BYTES);
    cudaFuncSetAttribute(gemm_bf16_cp,
                         cudaFuncAttributeMaxDynamicSharedMemorySize,
                         GEMM_SMEM_BYTES);

    bf16 *inb0, *inb1, *inb2, *wb0, *wb1, *wb2, *wb3;
    bf16 *pq, *pk, *pv, *ctxb;
    float *proj;
    cudaGetSymbolAddress((void**)&inb0, g_inb);
    inb1 = inb0 + (size_t)M_ROWS * DIM;
    inb2 = inb1 + (size_t)M_ROWS * DIM;
    cudaGetSymbolAddress((void**)&wb0, g_wb);
    wb1 = wb0 + (size_t)DIM * DIM;
    wb2 = wb1 + (size_t)DIM * DIM;
    wb3 = wb2 + (size_t)DIM * DIM;
    cudaGetSymbolAddress((void**)&pq,   g_pq);
    cudaGetSymbolAddress((void**)&pk,   g_pk);
    cudaGetSymbolAddress((void**)&pv,   g_pv);
    cudaGetSymbolAddress((void**)&ctxb, g_ctxb);
    cudaGetSymbolAddress((void**)&proj, g_proj);

    // ---- convert inputs + weights to bf16 ----
    CvtPtrs cv;
    cv.s[0] = query; cv.d[0] = inb0; cv.n[0] = M_ROWS * DIM;
    cv.s[1] = key;   cv.d[1] = inb1; cv.n[1] = M_ROWS * DIM;
    cv.s[2] = value; cv.d[2] = inb2; cv.n[2] = M_ROWS * DIM;
    cv.s[3] = Wq;    cv.d[3] = wb0;  cv.n[3] = DIM * DIM;
    cv.s[4] = Wk;    cv.d[4] = wb1;  cv.n[4] = DIM * DIM;
    cv.s[5] = Wv;    cv.d[5] = wb2;  cv.n[5] = DIM * DIM;
    cv.s[6] = Wo;    cv.d[6] = wb3;  cv.n[6] = DIM * DIM;
    cvt_kernel<<<dim3(M_ROWS * DIM / 1024, 7), 256>>>(cv);

    // ---- QKV projections (bf16 out) ----
    GemmPtrs g3;
    g3.A[0] = inb0; g3.W[0] = wb0; g3.bias[0] = bq; g3.Cb[0] = pq; g3.Cf[0] = nullptr;
    g3.A[1] = inb1; g3.W[1] = wb1; g3.bias[1] = bk; g3.Cb[1] = pk; g3.Cf[1] = nullptr;
    g3.A[2] = inb2; g3.W[2] = wb2; g3.bias[2] = bv; g3.Cb[2] = pv; g3.Cf[2] = nullptr;
    g3.write_f32 = 0;
    gemm_bf16_cp<<<dim3(8, 64, 3), 256, GEMM_SMEM_BYTES>>>(g3);

    attn_bf16_cp<<<dim3(NCHUNK, 8), 512, AT_SMEM_BYTES>>>(q_mask, k_mask);

    // ---- output projection (fp32 out) ----
    GemmPtrs g1;
    g1.A[0] = ctxb; g1.W[0] = wb3; g1.bias[0] = bo; g1.Cb[0] = nullptr; g1.Cf[0] = proj;
    g1.A[1] = ctxb; g1.W[1] = wb3; g1.bias[1] = bo; g1.Cb[1] = nullptr; g1.Cf[1] = proj;
    g1.A[2] = ctxb; g1.W[2] = wb3; g1.bias[2] = bo; g1.Cb[2] = nullptr; g1.Cf[2] = proj;
    g1.write_f32 = 1;
    gemm_bf16_cp<<<dim3(8, 64, 1), 256, GEMM_SMEM_BYTES>>>(g1);

    resid_ln_kernel<<<M_ROWS, 256>>>(query, gamma, beta, out);
}

// round 10
// speedup vs baseline: 4.5338x; 1.0657x over previous
#include <cuda_runtime.h>
#include <cuda_bf16.h>
#include <cstdint>
#include <math.h>

// ---------------------------------------------------------------------------
// B=8, L=1024, D=1024, H=16, d=64.  M = 8192 token rows.
// bf16 mma.sync + ldmatrix + deep cp.async pipelines; bf16 operands in gmem.
// ---------------------------------------------------------------------------

#define M_ROWS  8192
#define DIM     1024
#define NCHUNK  128
#define CHUNK_ELEMS 65536

typedef __nv_bfloat16 bf16;

__device__ bf16 g_inb[3][M_ROWS * DIM];
__device__ bf16 g_wb[4][DIM * DIM];
__device__ bf16 g_pq[M_ROWS * DIM];
__device__ bf16 g_pk[M_ROWS * DIM];
__device__ bf16 g_pv[M_ROWS * DIM];
__device__ bf16 g_ctxb[M_ROWS * DIM];
__device__ float g_proj[M_ROWS * DIM];

__device__ __forceinline__ uint32_t smem_u32(const void* p) {
    uint32_t a;
    asm("{ .reg .u64 t; cvta.to.shared.u64 t, %1; cvt.u32.u64 %0, t; }"
        : "=r"(a) : "l"(p));
    return a;
}
__device__ __forceinline__ uint32_t packbf(float a, float b) {
    __nv_bfloat162 t = __floats2bfloat162_rn(a, b);
    return *reinterpret_cast<uint32_t*>(&t);
}
__device__ __forceinline__ void mma_bf16(float* c, const uint32_t* a,
                                         const uint32_t* b) {
    asm volatile(
        "mma.sync.aligned.m16n8k16.row.col.f32.bf16.bf16.f32 "
        "{%0,%1,%2,%3}, {%4,%5,%6,%7}, {%8,%9}, {%0,%1,%2,%3};"
        : "+f"(c[0]), "+f"(c[1]), "+f"(c[2]), "+f"(c[3])
        : "r"(a[0]), "r"(a[1]), "r"(a[2]), "r"(a[3]), "r"(b[0]), "r"(b[1]));
}
#define LDM_X4(r0, r1, r2, r3, addr) \
    asm volatile("ldmatrix.sync.aligned.m8n8.x4.shared.b16 {%0,%1,%2,%3}, [%4];" \
        : "=r"(r0), "=r"(r1), "=r"(r2), "=r"(r3) : "r"(addr))
#define LDM_X4T(r0, r1, r2, r3, addr) \
    asm volatile("ldmatrix.sync.aligned.m8n8.x4.trans.shared.b16 {%0,%1,%2,%3}, [%4];" \
        : "=r"(r0), "=r"(r1), "=r"(r2), "=r"(r3) : "r"(addr))
#define CP16(dst, src) \
    asm volatile("cp.async.cg.shared.global [%0], [%1], 16;" \
        :: "r"(dst), "l"(src) : "memory")
#define CP_COMMIT() asm volatile("cp.async.commit_group;" ::: "memory")
#define CP_WAIT(n)  asm volatile("cp.async.wait_group %0;" :: "n"(n) : "memory")

// Swizzled tile: 128 rows x 32 bf16 (2048 words).
__device__ __forceinline__ uint32_t swz(int m, int k) {
    return (uint32_t)(((m >> 1) << 5)
        + (((((m & 1) << 2) | (k >> 3)) ^ ((m >> 1) & 7)) << 2)
        + ((k >> 1) & 3));
}

// ---------------------------------------------------------------------------
// fp32 -> bf16 conversion
// ---------------------------------------------------------------------------
struct CvtPtrs { const float* s[7]; bf16* d[7]; int n[7]; };

__global__ void __launch_bounds__(256) cvt_kernel(CvtPtrs cp)
{
    const int z = blockIdx.y;
    const int n = cp.n[z];
    const int idx = (blockIdx.x * 256 + threadIdx.x) * 4;
    if (idx >= n) return;
    float4 v = *(const float4*)(cp.s[z] + idx);
    *(uint32_t*)(cp.d[z] + idx)     = packbf(v.x, v.y);
    *(uint32_t*)(cp.d[z] + idx + 2) = packbf(v.z, v.w);
}

// ---------------------------------------------------------------------------
// bf16 GEMM, 4-stage cp.async ring: C = A @ W^T + bias.  CTA 128x128,
// 256 thr, warps 2m x 4n, K chunks of 32, 2 CTAs/SM.  z-batched.
// ---------------------------------------------------------------------------
struct GemmPtrs {
    const bf16* A[3]; const bf16* W[3]; const float* bias[3];
    bf16* Cb[3]; float* Cf[3]; int write_f32;
};
#define G_STAGE_BYTES 16384
#define GEMM_SMEM_BYTES (4 * G_STAGE_BYTES)   // 65536

__global__ void __launch_bounds__(256, 2) gemm_bf16_cp(GemmPtrs gp)
{
    extern __shared__ __align__(16) uint32_t smg[];
    const uint32_t sb = smem_u32(smg);
    const int z = blockIdx.z;
    const bf16* A     = gp.A[z];
    const bf16* W     = gp.W[z];
    const float* bias = gp.bias[z];

    const int tid  = threadIdx.x;
    const int lane = tid & 31;
    const int wid  = tid >> 5;
    const int wm   = wid & 1;
    const int wn   = wid >> 1;
    const int row0 = blockIdx.y * 128;
    const int col0 = blockIdx.x * 128;

    const int m  = tid & 127;
    const int h  = tid >> 7;
    const int k0 = h * 16;
    const bf16* Ap = A + (size_t)(row0 + m) * DIM + k0;
    const bf16* Wp = W + (size_t)(col0 + m) * DIM + k0;
    const uint32_t dA0 = sb + swz(m, k0) * 4;
    const uint32_t dA1 = sb + swz(m, k0 + 8) * 4;
    const uint32_t dB0 = sb + (2048 + swz(m, k0)) * 4;
    const uint32_t dB1 = sb + (2048 + swz(m, k0 + 8)) * 4;

    const int g = lane >> 3, li = lane & 7;
    const int aml = wm * 64 + (g & 1) * 8 + li;
    const int bnl = wn * 32 + ((g >> 1) & 1) * 8 + li;
    uint32_t aAddr[2], bAddr[2];
    #pragma unroll
    for (int ks = 0; ks < 2; ks++) {
        aAddr[ks] = sb + swz(aml, ks * 16 + (g >> 1) * 8) * 4;
        bAddr[ks] = sb + (2048 + swz(bnl, ks * 16 + (g & 1) * 8)) * 4;
    }

    float acc[4][4][4];
    #pragma unroll
    for (int mt = 0; mt < 4; mt++)
        #pragma unroll
        for (int nt = 0; nt < 4; nt++)
            #pragma unroll
            for (int f = 0; f < 4; f++) acc[mt][nt][f] = 0.0f;

    // prologue: stages 0..2
    #pragma unroll
    for (int s = 0; s < 3; s++) {
        const uint32_t so = (uint32_t)(s * G_STAGE_BYTES);
        const bf16* Ap2 = Ap + s * 32;
        const bf16* Wp2 = Wp + s * 32;
        CP16(dA0 + so, Ap2);     CP16(dA1 + so, Ap2 + 8);
        CP16(dB0 + so, Wp2);     CP16(dB1 + so, Wp2 + 8);
        CP_COMMIT();
    }

    for (int c = 0; c < 32; ++c) {
        CP_WAIT(2);
        __syncthreads();
        const uint32_t off = (uint32_t)((c & 3) * G_STAGE_BYTES);

        #pragma unroll
        for (int ks = 0; ks < 2; ks++) {
            uint32_t af[4][4], bfr[4][2];
            #pragma unroll
            for (int mt = 0; mt < 4; mt++)
                LDM_X4(af[mt][0], af[mt][1], af[mt][2], af[mt][3],
                       aAddr[ks] + off + mt * 1024);
            #pragma unroll
            for (int pr = 0; pr < 2; pr++) {
                uint32_t r0, r1, r2, r3;
                LDM_X4(r0, r1, r2, r3, bAddr[ks] + off + pr * 1024);
                bfr[pr * 2][0] = r0; bfr[pr * 2][1] = r1;
                bfr[pr * 2 + 1][0] = r2; bfr[pr * 2 + 1][1] = r3;
            }
            #pragma unroll
            for (int mt = 0; mt < 4; mt++)
                #pragma unroll
                for (int nt = 0; nt < 4; nt++)
                    mma_bf16(acc[mt][nt], af[mt], bfr[nt]);
        }

        if (c + 3 < 32) {
            const uint32_t so = (uint32_t)(((c + 3) & 3) * G_STAGE_BYTES);
            const bf16* Ap2 = Ap + (c + 3) * 32;
            const bf16* Wp2 = Wp + (c + 3) * 32;
            CP16(dA0 + so, Ap2);     CP16(dA1 + so, Ap2 + 8);
            CP16(dB0 + so, Wp2);     CP16(dB1 + so, Wp2 + 8);
        }
        CP_COMMIT();   // empty group in the tail keeps wait_group counting uniform
    }

    const int qr = lane >> 2;
    const int qc = (lane & 3) * 2;
    if (gp.write_f32) {
        float* C = gp.Cf[z];
        #pragma unroll
        for (int nt = 0; nt < 4; nt++) {
            const int cc = col0 + wn * 32 + nt * 8 + qc;
            const float b0 = bias[cc], b1 = bias[cc + 1];
            #pragma unroll
            for (int mt = 0; mt < 4; mt++) {
                const int rr = row0 + wm * 64 + mt * 16 + qr;
                *(float2*)(C + (size_t)rr * DIM + cc) =
                    make_float2(acc[mt][nt][0] + b0, acc[mt][nt][1] + b1);
                *(float2*)(C + (size_t)(rr + 8) * DIM + cc) =
                    make_float2(acc[mt][nt][2] + b0, acc[mt][nt][3] + b1);
            }
        }
    } else {
        bf16* C = gp.Cb[z];
        #pragma unroll
        for (int nt = 0; nt < 4; nt++) {
            const int cc = col0 + wn * 32 + nt * 8 + qc;
            const float b0 = bias[cc], b1 = bias[cc + 1];
            #pragma unroll
            for (int mt = 0; mt < 4; mt++) {
                const int rr = row0 + wm * 64 + mt * 16 + qr;
                *(uint32_t*)(C + (size_t)rr * DIM + cc) =
                    packbf(acc[mt][nt][0] + b0, acc[mt][nt][1] + b1);
                *(uint32_t*)(C + (size_t)(rr + 8) * DIM + cc) =
                    packbf(acc[mt][nt][2] + b0, acc[mt][nt][3] + b1);
            }
        }
    }
}

// ---------------------------------------------------------------------------
// Attention, bf16 mma + ldmatrix + double-buffered cp.async K/V.
// 512 thr (16 warps, 4m x 4n).  Masks in registers.
// Smem words: Qs[4096] | Ks[2x4096] | Vs[2x4096] | Ps[8192] | rowsum[128]
// ---------------------------------------------------------------------------
#define AT_KS 4096
#define AT_VS 12288
#define AT_PS 20480
#define AT_RS 28672
#define AT_WORDS 28800
#define AT_SMEM_BYTES (AT_WORDS * 4)   // 115200

__global__ void __launch_bounds__(512) attn_bf16_cp(
    const float* __restrict__ qmask, const float* __restrict__ kmask)
{
    extern __shared__ __align__(16) uint32_t smw[];
    const uint32_t sbb = smem_u32(smw);
    float* rowsum = (float*)(smw + AT_RS);

    const int tid  = threadIdx.x;
    const int lane = tid & 31;
    const int wid  = tid >> 5;
    const int wm   = wid & 3;
    const int wn   = wid >> 2;
    const int r    = blockIdx.x;
    const int qt   = blockIdx.y;

    const bf16* Qc = g_pq + (size_t)r * CHUNK_ELEMS + qt * 8192;
    const bf16* Kc = g_pk + (size_t)r * CHUNK_ELEMS;
    const bf16* Vc = g_pv + (size_t)r * CHUNK_ELEMS;
    const float* qmb = qmask + (r & 7) * 1024 + qt * 128;
    const float* kmb = kmask + (r & 7) * 1024;

    const int lm = tid & 127;
    const int lq = tid >> 7;
    const int lk = lq * 16;
    const uint32_t lw0 = ((lk >> 5) * 2048 + swz(lm, lk & 31)) * 4;
    const uint32_t lw1 = ((lk >> 5) * 2048 + swz(lm, (lk & 31) + 8)) * 4;

    // prologue: Q + K/V stage 0
    CP16(sbb + lw0, Qc + lm * 64 + lk);
    CP16(sbb + lw1, Qc + lm * 64 + lk + 8);
    {
        const bf16* ks_ = Kc + lm * 64 + lk;
        const bf16* vs_ = Vc + lm * 64 + lk;
        CP16(sbb + AT_KS * 4 + lw0, ks_);
        CP16(sbb + AT_KS * 4 + lw1, ks_ + 8);
        CP16(sbb + AT_VS * 4 + lw0, vs_);
        CP16(sbb + AT_VS * 4 + lw1, vs_ + 8);
    }
    CP_COMMIT();
    if (tid < 128) rowsum[tid] = 0.0f;

    // per-thread masks (q rows fixed)
    float qm0[2], qm1[2];
    #pragma unroll
    for (int mt = 0; mt < 2; mt++) {
        const int row = wm * 32 + mt * 16 + (lane >> 2);
        qm0[mt] = qmb[row];
        qm1[mt] = qmb[row + 8];
    }

    const int g = lane >> 3, li = lane & 7;

    float oacc[2][2][4];
    #pragma unroll
    for (int mt = 0; mt < 2; mt++)
        #pragma unroll
        for (int nd = 0; nd < 2; nd++)
            #pragma unroll
            for (int f = 0; f < 4; f++) oacc[mt][nd][f] = 0.0f;
    float rs0[2] = {0, 0}, rs1[2] = {0, 0};

    for (int kt = 0; kt < 8; kt++) {
        CP_WAIT(0);
        __syncthreads();   // stage kt visible everywhere; all PV(kt-1) readers done

        if (kt + 1 < 8) {  // issue stage kt+1 (lands during this iter's compute)
            const uint32_t so = (uint32_t)(((kt + 1) & 1) * 16384);
            const bf16* ks_ = Kc + (kt + 1) * 8192 + lm * 64 + lk;
            const bf16* vs_ = Vc + (kt + 1) * 8192 + lm * 64 + lk;
            CP16(sbb + AT_KS * 4 + so + lw0, ks_);
            CP16(sbb + AT_KS * 4 + so + lw1, ks_ + 8);
            CP16(sbb + AT_VS * 4 + so + lw0, vs_);
            CP16(sbb + AT_VS * 4 + so + lw1, vs_ + 8);
            CP_COMMIT();
        }

        // k masks for this tile (registers; hidden under S compute)
        float km0[4], km1[4];
        #pragma unroll
        for (int nt = 0; nt < 4; nt++) {
            const int colp = wn * 16 + nt * 4 + (lane & 3);
            km0[nt] = kmb[kt * 128 + 2 * colp];
            km1[nt] = kmb[kt * 128 + 2 * colp + 1];
        }

        const uint32_t kvo = (uint32_t)((kt & 1) * 16384);

        // ---- S = Q K^T ----
        float sacc[2][4][4];
        #pragma unroll
        for (int mt = 0; mt < 2; mt++)
            #pragma unroll
            for (int nt = 0; nt < 4; nt++)
                #pragma unroll
                for (int f = 0; f < 4; f++) sacc[mt][nt][f] = 0.0f;

        #pragma unroll
        for (int ks = 0; ks < 4; ks++) {
            uint32_t af[2][4], bfr[4][2];
            #pragma unroll
            for (int mt = 0; mt < 2; mt++) {
                const int ml = wm * 32 + mt * 16 + (g & 1) * 8 + li;
                const int kl = ks * 16 + (g >> 1) * 8;
                const uint32_t ad = sbb + ((kl >> 5) * 2048 + swz(ml, kl & 31)) * 4;
                LDM_X4(af[mt][0], af[mt][1], af[mt][2], af[mt][3], ad);
            }
            #pragma unroll
            for (int pr = 0; pr < 2; pr++) {
                const int nl = wn * 32 + pr * 16 + ((g >> 1) & 1) * 8 + li;
                const int kl = ks * 16 + (g & 1) * 8;
                const uint32_t ad = sbb + AT_KS * 4 + kvo
                                    + ((kl >> 5) * 2048 + swz(nl, kl & 31)) * 4;
                uint32_t r0, r1, r2, r3;
                LDM_X4(r0, r1, r2, r3, ad);
                bfr[pr * 2][0] = r0; bfr[pr * 2][1] = r1;
                bfr[pr * 2 + 1][0] = r2; bfr[pr * 2 + 1][1] = r3;
            }
            #pragma unroll
            for (int mt = 0; mt < 2; mt++)
                #pragma unroll
                for (int nt = 0; nt < 4; nt++)
                    mma_bf16(sacc[mt][nt], af[mt], bfr[nt]);
        }

        // ---- P = mask ? exp(S/8) : 0 ; store packed to Ps ----
        #pragma unroll
        for (int mt = 0; mt < 2; mt++) {
            const int row = wm * 32 + mt * 16 + (lane >> 2);
            #pragma unroll
            for (int nt = 0; nt < 4; nt++) {
                const int colp = wn * 16 + nt * 4 + (lane & 3);
                float p0 = (qm0[mt] * km0[nt] == 0.0f) ? 0.0f : __expf(sacc[mt][nt][0] * 0.125f);
                float p1 = (qm0[mt] * km1[nt] == 0.0f) ? 0.0f : __expf(sacc[mt][nt][1] * 0.125f);
                float p2 = (qm1[mt] * km0[nt] == 0.0f) ? 0.0f : __expf(sacc[mt][nt][2] * 0.125f);
                float p3 = (qm1[mt] * km1[nt] == 0.0f) ? 0.0f : __expf(sacc[mt][nt][3] * 0.125f);
                uint32_t w0 = packbf(p0, p1);
                uint32_t w1 = packbf(p2, p3);
                float2 f0 = __bfloat1622float2(*(__nv_bfloat162*)&w0);
                float2 f1 = __bfloat1622float2(*(__nv_bfloat162*)&w1);
                rs0[mt] += f0.x + f0.y;
                rs1[mt] += f1.x + f1.y;
                const int tile = colp >> 4;
                const int kk = (colp & 15) * 2;
                smw[AT_PS + tile * 2048 + swz(row, kk)]     = w0;
                smw[AT_PS + tile * 2048 + swz(row + 8, kk)] = w1;
            }
        }
        __syncthreads();

        // ---- O += P V ----
        #pragma unroll
        for (int kb = 0; kb < 8; kb++) {
            uint32_t pa[2][4], vb[2][2];
            #pragma unroll
            for (int mt = 0; mt < 2; mt++) {
                const int ml = wm * 32 + mt * 16 + (g & 1) * 8 + li;
                const int kl = kb * 16 + (g >> 1) * 8;
                const uint32_t ad = sbb + AT_PS * 4
                                    + ((kl >> 5) * 2048 + swz(ml, kl & 31)) * 4;
                LDM_X4(pa[mt][0], pa[mt][1], pa[mt][2], pa[mt][3], ad);
            }
            {
                const int rowl = kb * 16 + (g & 1) * 8 + li;
                const int dl   = wn * 16 + (g >> 1) * 8;
                const uint32_t ad = sbb + AT_VS * 4 + kvo
                                    + ((dl >> 5) * 2048 + swz(rowl, dl & 31)) * 4;
                uint32_t r0, r1, r2, r3;
                LDM_X4T(r0, r1, r2, r3, ad);
                vb[0][0] = r0; vb[0][1] = r1;
                vb[1][0] = r2; vb[1][1] = r3;
            }
            #pragma unroll
            for (int mt = 0; mt < 2; mt++)
                #pragma unroll
                for (int nd = 0; nd < 2; nd++)
                    mma_bf16(oacc[mt][nd], pa[mt], vb[nd]);
        }
    }

    // ---- rowsum reduction ----
    #pragma unroll
    for (int mt = 0; mt < 2; mt++) {
        float v0 = rs0[mt], v1 = rs1[mt];
        v0 += __shfl_xor_sync(0xffffffffu, v0, 1);
        v0 += __shfl_xor_sync(0xffffffffu, v0, 2);
        v1 += __shfl_xor_sync(0xffffffffu, v1, 1);
        v1 += __shfl_xor_sync(0xffffffffu, v1, 2);
        if ((lane & 3) == 0) {
            const int row = wm * 32 + mt * 16 + (lane >> 2);
            atomicAdd(&rowsum[row], v0);
            atomicAdd(&rowsum[row + 8], v1);
        }
    }
    __syncthreads();

    // ---- normalize + store bf16 ctx ----
    bf16* Oc = g_ctxb + (size_t)r * CHUNK_ELEMS + qt * 8192;
    #pragma unroll
    for (int mt = 0; mt < 2; mt++) {
        const int row = wm * 32 + mt * 16 + (lane >> 2);
        const float inv0 = 1.0f / fmaxf(rowsum[row], 2e-15f);
        const float inv1 = 1.0f / fmaxf(rowsum[row + 8], 2e-15f);
        #pragma unroll
        for (int nd = 0; nd < 2; nd++) {
            const int col = wn * 16 + nd * 8 + 2 * (lane & 3);
            *(uint32_t*)(Oc + row * 64 + col) =
                packbf(oacc[mt][nd][0] * inv0, oacc[mt][nd][1] * inv0);
            *(uint32_t*)(Oc + (row + 8) * 64 + col) =
                packbf(oacc[mt][nd][2] * inv1, oacc[mt][nd][3] * inv1);
        }
    }
}

// ---------------------------------------------------------------------------
// Residual + LayerNorm (unchanged)
// ---------------------------------------------------------------------------
__global__ void __launch_bounds__(256) resid_ln_kernel(
    const float* __restrict__ resid, const float* __restrict__ gamma,
    const float* __restrict__ beta, float* __restrict__ out)
{
    __shared__ float red[8];
    __shared__ float bc;

    const int row = blockIdx.x;
    const int tid = threadIdx.x;
    const float* pr = g_proj + (size_t)row * 1024;
    const float* rr = resid + (size_t)row * 1024;

    float x[4];
    float sum = 0.0f;
    #pragma unroll
    for (int c = 0; c < 4; c++) {
        x[c] = rr[tid + 256 * c] + pr[tid + 256 * c];
        sum += x[c];
    }
    #pragma unroll
    for (int m = 16; m; m >>= 1) sum += __shfl_xor_sync(0xffffffffu, sum, m);
    if ((tid & 31) == 0) red[tid >> 5] = sum;
    __syncthreads();
    if (tid == 0) {
        float t = 0.0f;
        #pragma unroll
        for (int i = 0; i < 8; i++) t += red[i];
        bc = t;
    }
    __syncthreads();
    const float mean = bc * (1.0f / 1024.0f);

    float vs = 0.0f;
    #pragma unroll
    for (int c = 0; c < 4; c++) { float d = x[c] - mean; vs += d * d; }
    #pragma unroll
    for (int m = 16; m; m >>= 1) vs += __shfl_xor_sync(0xffffffffu, vs, m);
    __syncthreads();
    if ((tid & 31) == 0) red[tid >> 5] = vs;
    __syncthreads();
    if (tid == 0) {
        float t = 0.0f;
        #pragma unroll
        for (int i = 0; i < 8; i++) t += red[i];
        bc = t;
    }
    __syncthreads();
    const float var = bc * (1.0f / 1024.0f);
    const float inv = rsqrtf(var + 1e-5f);

    #pragma unroll
    for (int c = 0; c < 4; c++) {
        int idx = tid + 256 * c;
        out[(size_t)row * 1024 + idx] =
            (x[c] - mean) * inv * gamma[idx] + beta[idx];
    }
}

// ---------------------------------------------------------------------------
// Host launcher
// ---------------------------------------------------------------------------
extern "C" void kernel_launch(void* const* d_in, const int* in_sizes, int n_in,
                              void* d_out, int out_size)
{
    const float* query  = (const float*)d_in[0];
    const float* key    = (const float*)d_in[1];
    const float* value  = (const float*)d_in[2];
    const float* q_mask = (const float*)d_in[3];
    const float* k_mask = (const float*)d_in[4];
    const float* Wq     = (const float*)d_in[5];
    const float* bq     = (const float*)d_in[6];
    const float* Wk     = (const float*)d_in[7];
    const float* bk     = (const float*)d_in[8];
    const float* Wv     = (const float*)d_in[9];
    const float* bv     = (const float*)d_in[10];
    const float* Wo     = (const float*)d_in[11];
    const float* bo     = (const float*)d_in[12];
    const float* gamma  = (const float*)d_in[13];
    const float* beta   = (const float*)d_in[14];
    float* out = (float*)d_out;

    (void)in_sizes; (void)n_in; (void)out_size;

    cudaFuncSetAttribute(attn_bf16_cp,
                         cudaFuncAttributeMaxDynamicSharedMemorySize,
                         AT_SMEM_BYTES);
    cudaFuncSetAttribute(gemm_bf16_cp,
                         cudaFuncAttributeMaxDynamicSharedMemorySize,
                         GEMM_SMEM_BYTES);

    bf16 *inb0, *inb1, *inb2, *wb0, *wb1, *wb2, *wb3;
    bf16 *pq, *pk, *pv, *ctxb;
    float *proj;
    cudaGetSymbolAddress((void**)&inb0, g_inb);
    inb1 = inb0 + (size_t)M_ROWS * DIM;
    inb2 = inb1 + (size_t)M_ROWS * DIM;
    cudaGetSymbolAddress((void**)&wb0, g_wb);
    wb1 = wb0 + (size_t)DIM * DIM;
    wb2 = wb1 + (size_t)DIM * DIM;
    wb3 = wb2 + (size_t)DIM * DIM;
    cudaGetSymbolAddress((void**)&pq,   g_pq);
    cudaGetSymbolAddress((void**)&pk,   g_pk);
    cudaGetSymbolAddress((void**)&pv,   g_pv);
    cudaGetSymbolAddress((void**)&ctxb, g_ctxb);
    cudaGetSymbolAddress((void**)&proj, g_proj);

    CvtPtrs cv;
    cv.s[0] = query; cv.d[0] = inb0; cv.n[0] = M_ROWS * DIM;
    cv.s[1] = key;   cv.d[1] = inb1; cv.n[1] = M_ROWS * DIM;
    cv.s[2] = value; cv.d[2] = inb2; cv.n[2] = M_ROWS * DIM;
    cv.s[3] = Wq;    cv.d[3] = wb0;  cv.n[3] = DIM * DIM;
    cv.s[4] = Wk;    cv.d[4] = wb1;  cv.n[4] = DIM * DIM;
    cv.s[5] = Wv;    cv.d[5] = wb2;  cv.n[5] = DIM * DIM;
    cv.s[6] = Wo;    cv.d[6] = wb3;  cv.n[6] = DIM * DIM;
    cvt_kernel<<<dim3(M_ROWS * DIM / 1024, 7), 256>>>(cv);

    GemmPtrs g3;
    g3.A[0] = inb0; g3.W[0] = wb0; g3.bias[0] = bq; g3.Cb[0] = pq; g3.Cf[0] = nullptr;
    g3.A[1] = inb1; g3.W[1] = wb1; g3.bias[1] = bk; g3.Cb[1] = pk; g3.Cf[1] = nullptr;
    g3.A[2] = inb2; g3.W[2] = wb2; g3.bias[2] = bv; g3.Cb[2] = pv; g3.Cf[2] = nullptr;
    g3.write_f32 = 0;
    gemm_bf16_cp<<<dim3(8, 64, 3), 256, GEMM_SMEM_BYTES>>>(g3);

    attn_bf16_cp<<<dim3(NCHUNK, 8), 512, AT_SMEM_BYTES>>>(q_mask, k_mask);

    GemmPtrs g1;
    g1.A[0] = ctxb; g1.W[0] = wb3; g1.bias[0] = bo; g1.Cb[0] = nullptr; g1.Cf[0] = proj;
    g1.A[1] = ctxb; g1.W[1] = wb3; g1.bias[1] = bo; g1.Cb[1] = nullptr; g1.Cf[1] = proj;
    g1.A[2] = ctxb; g1.W[2] = wb3; g1.bias[2] = bo; g1.Cb[2] = nullptr; g1.Cf[2] = proj;
    g1.write_f32 = 1;
    gemm_bf16_cp<<<dim3(8, 64, 1), 256, GEMM_SMEM_BYTES>>>(g1);

    resid_ln_kernel<<<M_ROWS, 256>>>(query, gamma, beta, out);
}